// round 1
// baseline (speedup 1.0000x reference)
#include <cuda_runtime.h>
#include <cuda_bf16.h>
#include <math.h>

// ----------------------------------------------------------------------------
// Problem constants (fixed by the reference):
//   TOTAL = 131072 frames, SEG = 256 segments, FEAT = 78, HID = 1024, NCLS = 10
// Input order (metadata.txt):
//   0:x 1:W1 2:b1 3:W2 4:b2 5:W3 6:b3 7:W4 8:b4 9:W5 10:b5 11:W6 12:b6 13:W7 14:b7 15:lengths
// Output: [256, 10] float32
// ----------------------------------------------------------------------------

#define TOTAL_N 131072
#define HID     1024
#define FEAT    78
#define NSEG    256
#define NCLS    10

// Scratch (static __device__ globals; no allocation in kernel_launch)
__device__ float g_bufA[(size_t)TOTAL_N * HID];   // 512 MB
__device__ float g_bufB[(size_t)TOTAL_N * HID];   // 512 MB
__device__ float g_scores[TOTAL_N];
__device__ float g_pooled[NSEG * HID];
__device__ float g_tmp6[NSEG * HID];

// ----------------------------------------------------------------------------
// Generic tiled fp32 GEMM + bias + optional ReLU.
// C[N x M] = act(A[N x K] @ B[K x M] + bias[M])
// Tile 64x64, K-tile 16, 16x16 threads, 4x4 micro-tile per thread.
// Requires N % 64 == 0 and M % 64 == 0 (true for all stages here); K arbitrary.
// ----------------------------------------------------------------------------
#define TILE 64
#define KT   16

__global__ __launch_bounds__(256) void gemm_bias_act_kernel(
    const float* __restrict__ A, const float* __restrict__ B,
    const float* __restrict__ bias, float* __restrict__ C,
    int N, int K, int M, int do_relu)
{
    __shared__ float As[KT][TILE + 1];  // As[k][row], padded vs bank conflicts
    __shared__ float Bs[KT][TILE];      // Bs[k][col], rows are 256B-aligned

    const int tx = threadIdx.x;              // 0..15 -> output cols
    const int ty = threadIdx.y;              // 0..15 -> output rows
    const int tid = ty * 16 + tx;            // 0..255
    const int row0 = blockIdx.y * TILE;
    const int col0 = blockIdx.x * TILE;

    // load indices
    const int ar = tid >> 4;   // 0..15 (A tile row group)
    const int ak = tid & 15;   // 0..15 (A tile k)
    const int bc = tid & 63;   // 0..63 (B tile col)
    const int bk = tid >> 6;   // 0..3  (B tile k group)

    float acc[4][4];
    #pragma unroll
    for (int i = 0; i < 4; i++)
        #pragma unroll
        for (int j = 0; j < 4; j++) acc[i][j] = 0.f;

    for (int k0 = 0; k0 < K; k0 += KT) {
        // Load A tile: 64 rows x 16 k, stored transposed As[k][row]
        #pragma unroll
        for (int q = 0; q < 4; q++) {
            const int r = ar + q * 16;
            const int gk = k0 + ak;
            As[ak][r] = (gk < K) ? A[(size_t)(row0 + r) * K + gk] : 0.f;
        }
        // Load B tile: 16 k x 64 cols
        #pragma unroll
        for (int q = 0; q < 4; q++) {
            const int kk = bk + q * 4;
            const int gk = k0 + kk;
            Bs[kk][bc] = (gk < K) ? B[(size_t)gk * M + (col0 + bc)] : 0.f;
        }
        __syncthreads();

        #pragma unroll
        for (int kk = 0; kk < KT; kk++) {
            float a[4];
            #pragma unroll
            for (int i = 0; i < 4; i++) a[i] = As[kk][ty * 4 + i];
            const float4 bv = *reinterpret_cast<const float4*>(&Bs[kk][tx * 4]);
            const float b[4] = {bv.x, bv.y, bv.z, bv.w};
            #pragma unroll
            for (int i = 0; i < 4; i++)
                #pragma unroll
                for (int j = 0; j < 4; j++)
                    acc[i][j] = fmaf(a[i], b[j], acc[i][j]);
        }
        __syncthreads();
    }

    #pragma unroll
    for (int i = 0; i < 4; i++) {
        const int r = row0 + ty * 4 + i;
        #pragma unroll
        for (int j = 0; j < 4; j++) {
            const int c = col0 + tx * 4 + j;
            float v = acc[i][j] + bias[c];
            if (do_relu) v = fmaxf(v, 0.f);
            C[(size_t)r * M + c] = v;
        }
    }
}

// ----------------------------------------------------------------------------
// Attention-logit GEMV: scores[n] = relu( H[n,:] . W5[:,0] + b5 )
// One warp per row.
// ----------------------------------------------------------------------------
__global__ __launch_bounds__(256) void scores_kernel(
    const float* __restrict__ H, const float* __restrict__ W5,
    const float* __restrict__ b5, float* __restrict__ scores, int N)
{
    const int gwarp = (blockIdx.x * blockDim.x + threadIdx.x) >> 5;
    const int lane = threadIdx.x & 31;
    if (gwarp >= N) return;
    const float* h = H + (size_t)gwarp * HID;
    float s = 0.f;
    #pragma unroll 8
    for (int i = lane; i < HID; i += 32) s = fmaf(h[i], W5[i], s);
    #pragma unroll
    for (int o = 16; o > 0; o >>= 1) s += __shfl_xor_sync(0xffffffffu, s, o);
    if (lane == 0) scores[gwarp] = fmaxf(s + b5[0], 0.f);
}

// ----------------------------------------------------------------------------
// Ragged segment softmax + weighted pooling.
// grid = (HID/256, NSEG); block = 256. Each block handles 256 dims of 1 segment.
// ----------------------------------------------------------------------------
__global__ __launch_bounds__(256) void attnpool_kernel(
    const float* __restrict__ H, const float* __restrict__ scores,
    const int* __restrict__ lengths, float* __restrict__ pooled)
{
    const int seg = blockIdx.y;
    const int t = threadIdx.x;
    const int d = blockIdx.x * 256 + t;

    // segment start offset (tiny serial scan; 256 ints, cached)
    int start = 0;
    for (int s = 0; s < seg; s++) start += lengths[s];
    const int len = lengths[seg];

    __shared__ float red[256];

    // pass 1: max
    float m = -INFINITY;
    for (int i = t; i < len; i += 256) m = fmaxf(m, scores[start + i]);
    red[t] = m; __syncthreads();
    #pragma unroll
    for (int o = 128; o > 0; o >>= 1) {
        if (t < o) red[t] = fmaxf(red[t], red[t + o]);
        __syncthreads();
    }
    m = red[0]; __syncthreads();

    // pass 2: denom
    float ds = 0.f;
    for (int i = t; i < len; i += 256) ds += __expf(scores[start + i] - m);
    red[t] = ds; __syncthreads();
    #pragma unroll
    for (int o = 128; o > 0; o >>= 1) {
        if (t < o) red[t] += red[t + o];
        __syncthreads();
    }
    const float denom = red[0];

    // pass 3: weighted sum along this block's dims (unroll x4 for MLP)
    const float* __restrict__ hp = H + (size_t)start * HID + d;
    const float* __restrict__ sp = scores + start;
    float acc = 0.f;
    int i = 0;
    for (; i + 4 <= len; i += 4) {
        const float w0 = __expf(sp[i + 0] - m);
        const float w1 = __expf(sp[i + 1] - m);
        const float w2 = __expf(sp[i + 2] - m);
        const float w3 = __expf(sp[i + 3] - m);
        const float h0 = hp[(size_t)(i + 0) * HID];
        const float h1 = hp[(size_t)(i + 1) * HID];
        const float h2 = hp[(size_t)(i + 2) * HID];
        const float h3 = hp[(size_t)(i + 3) * HID];
        acc = fmaf(w0, h0, acc);
        acc = fmaf(w1, h1, acc);
        acc = fmaf(w2, h2, acc);
        acc = fmaf(w3, h3, acc);
    }
    for (; i < len; i++)
        acc = fmaf(__expf(sp[i] - m), hp[(size_t)i * HID], acc);

    pooled[seg * HID + d] = acc / denom;
}

// ----------------------------------------------------------------------------
// Final head: out[row, j] = T[row,:] . W7[:, j] + b7[j]   (no relu)
// grid = 256 rows; block = (32, 10): one warp per output class.
// ----------------------------------------------------------------------------
__global__ void final_kernel(
    const float* __restrict__ T, const float* __restrict__ W7,
    const float* __restrict__ b7, float* __restrict__ out)
{
    const int row = blockIdx.x;
    const int j = threadIdx.y;     // 0..9
    const int lane = threadIdx.x;  // 0..31
    const float* tr = T + (size_t)row * HID;
    float s = 0.f;
    #pragma unroll 8
    for (int k = lane; k < HID; k += 32) s = fmaf(tr[k], W7[k * NCLS + j], s);
    #pragma unroll
    for (int o = 16; o > 0; o >>= 1) s += __shfl_xor_sync(0xffffffffu, s, o);
    if (lane == 0) out[row * NCLS + j] = s + b7[j];
}

// ----------------------------------------------------------------------------
// Launcher
// ----------------------------------------------------------------------------
extern "C" void kernel_launch(void* const* d_in, const int* in_sizes, int n_in,
                              void* d_out, int out_size)
{
    const float* x  = (const float*)d_in[0];
    const float* W1 = (const float*)d_in[1];
    const float* b1 = (const float*)d_in[2];
    const float* W2 = (const float*)d_in[3];
    const float* b2 = (const float*)d_in[4];
    const float* W3 = (const float*)d_in[5];
    const float* b3 = (const float*)d_in[6];
    const float* W4 = (const float*)d_in[7];
    const float* b4 = (const float*)d_in[8];
    const float* W5 = (const float*)d_in[9];
    const float* b5 = (const float*)d_in[10];
    const float* W6 = (const float*)d_in[11];
    const float* b6 = (const float*)d_in[12];
    const float* W7 = (const float*)d_in[13];
    const float* b7 = (const float*)d_in[14];
    const int* lengths = (const int*)d_in[15];
    float* out = (float*)d_out;

    float *bufA, *bufB, *scores, *pooled, *tmp6;
    cudaGetSymbolAddress((void**)&bufA,   g_bufA);
    cudaGetSymbolAddress((void**)&bufB,   g_bufB);
    cudaGetSymbolAddress((void**)&scores, g_scores);
    cudaGetSymbolAddress((void**)&pooled, g_pooled);
    cudaGetSymbolAddress((void**)&tmp6,   g_tmp6);

    const dim3 block(16, 16);
    const dim3 gridBig(HID / TILE, TOTAL_N / TILE);   // (16, 2048)
    const dim3 gridSmall(HID / TILE, NSEG / TILE);    // (16, 4)

    // Layer 1: x[131072,78] @ W1[78,1024] -> bufA (relu)
    gemm_bias_act_kernel<<<gridBig, block>>>(x, W1, b1, bufA, TOTAL_N, FEAT, HID, 1);
    // Layer 2: bufA @ W2 -> bufB (relu)
    gemm_bias_act_kernel<<<gridBig, block>>>(bufA, W2, b2, bufB, TOTAL_N, HID, HID, 1);
    // Layer 3: bufB @ W3 -> bufA (relu)
    gemm_bias_act_kernel<<<gridBig, block>>>(bufB, W3, b3, bufA, TOTAL_N, HID, HID, 1);
    // Layer 4: bufA @ W4 -> bufB (relu)  == H4
    gemm_bias_act_kernel<<<gridBig, block>>>(bufA, W4, b4, bufB, TOTAL_N, HID, HID, 1);

    // Attention logits: scores[n] = relu(H4 . W5 + b5)
    scores_kernel<<<(TOTAL_N * 32 + 255) / 256, 256>>>(bufB, W5, b5, scores, TOTAL_N);

    // Segment softmax + weighted pooling -> pooled[256,1024]
    attnpool_kernel<<<dim3(HID / 256, NSEG), 256>>>(bufB, scores, lengths, pooled);

    // Head: tmp6 = relu(pooled @ W6 + b6)
    gemm_bias_act_kernel<<<gridSmall, block>>>(pooled, W6, b6, tmp6, NSEG, HID, HID, 1);

    // out = tmp6 @ W7 + b7
    final_kernel<<<NSEG, dim3(32, NCLS)>>>(tmp6, W7, b7, out);

    (void)in_sizes; (void)n_in; (void)out_size;
}

// round 3
// speedup vs baseline: 2.5836x; 2.5836x over previous
#include <cuda_runtime.h>
#include <cuda_bf16.h>
#include <math.h>
#include <stdint.h>

// ----------------------------------------------------------------------------
// Dnn_with_Attention on sm_103 (family-generic target: NO tcgen05, NO a-suffix
// features). Tensor path: mma.sync.m16n8k16 bf16 (HMMA), hi/lo split (3 MMAs),
// fp32 accumulate. cp.async 3-stage pipeline.
// ----------------------------------------------------------------------------

#define TOTAL_N 131072
#define HID     1024
#define FEAT    78
#define K1P     128
#define NSEG    256
#define NCLS    10

#define BM 128
#define BN 128
#define BKC 32                       // K elems per chunk
#define STAGES 3
#define ROWB 80                      // 32 bf16 = 64B + 16B pad (conflict-free)
#define MAT_BYTES (128 * ROWB)       // 10240 per matrix-half tile
#define STAGE_BYTES (4 * MAT_BYTES)  // A_hi A_lo B_hi B_lo
#define GEMM_SMEM (STAGES * STAGE_BYTES)   // 122880

typedef __nv_bfloat16 bf16;

// ------------------------------- scratch -----------------------------------
__device__ bf16 g_xp_hi[(size_t)TOTAL_N * K1P];
__device__ bf16 g_xp_lo[(size_t)TOTAL_N * K1P];
__device__ bf16 g_A_hi[(size_t)TOTAL_N * HID];
__device__ bf16 g_A_lo[(size_t)TOTAL_N * HID];
__device__ bf16 g_B_hi[(size_t)TOTAL_N * HID];
__device__ bf16 g_B_lo[(size_t)TOTAL_N * HID];
__device__ bf16 g_W1t_hi[HID * K1P];
__device__ bf16 g_W1t_lo[HID * K1P];
__device__ bf16 g_Wt_hi[3][HID * HID];
__device__ bf16 g_Wt_lo[3][HID * HID];
__device__ float g_scores[TOTAL_N];
__device__ float g_pooled[NSEG * HID];
__device__ float g_tmp6[NSEG * HID];

// ------------------------------ helpers ------------------------------------
__device__ __forceinline__ uint32_t smem_u32(const void* p) {
    uint32_t a;
    asm("{ .reg .u64 t; cvta.to.shared.u64 t, %1; cvt.u32.u64 %0, t; }"
        : "=r"(a) : "l"(p));
    return a;
}
__device__ __forceinline__ void cp16(uint32_t dst, const void* src) {
    asm volatile("cp.async.cg.shared.global [%0], [%1], 16;"
                 :: "r"(dst), "l"(src) : "memory");
}
__device__ __forceinline__ void cp_commit() {
    asm volatile("cp.async.commit_group;" ::: "memory");
}
template <int N>
__device__ __forceinline__ void cp_wait() {
    asm volatile("cp.async.wait_group %0;" :: "n"(N) : "memory");
}
__device__ __forceinline__ void mma_bf16(float* c, const uint32_t* a,
                                         const uint32_t* b) {
    asm volatile(
        "mma.sync.aligned.m16n8k16.row.col.f32.bf16.bf16.f32 "
        "{%0,%1,%2,%3}, {%4,%5,%6,%7}, {%8,%9}, {%0,%1,%2,%3};"
        : "+f"(c[0]), "+f"(c[1]), "+f"(c[2]), "+f"(c[3])
        : "r"(a[0]), "r"(a[1]), "r"(a[2]), "r"(a[3]), "r"(b[0]), "r"(b[1]));
}
__device__ __forceinline__ uint32_t lds_u32(const char* p) {
    return *reinterpret_cast<const uint32_t*>(p);
}
__device__ __forceinline__ void split2(float v, bf16& h, bf16& l) {
    h = __float2bfloat16(v);
    l = __float2bfloat16(v - __bfloat162float(h));
}
__device__ __forceinline__ uint32_t pack2(float v0, float v1) {
    bf16 h0 = __float2bfloat16(v0), h1 = __float2bfloat16(v1);
    return ((uint32_t)__bfloat16_as_ushort(h1) << 16) | __bfloat16_as_ushort(h0);
}

// ----------------------------------------------------------------------------
// HMMA GEMM: C[M,1024] = relu(A[M,K] @ Bt[1024,K]^T + bias), hi/lo split.
// grid = (1024/BN, M/BM), block = 256 (8 warps, each 64x32).
// ----------------------------------------------------------------------------
__global__ void __launch_bounds__(256) gemm_mma_kernel(
    const bf16* __restrict__ Ahi, const bf16* __restrict__ Alo,
    const bf16* __restrict__ Bthi, const bf16* __restrict__ Btlo,
    const float* __restrict__ bias,
    bf16* __restrict__ Chi, bf16* __restrict__ Clo, int K)
{
    extern __shared__ char smem[];
    const int tid = threadIdx.x;
    const int lane = tid & 31;
    const int wid = tid >> 5;
    const int gr = lane >> 2;          // fragment row within 8-group
    const int gcb = (lane & 3) * 4;    // byte offset of k-pair
    const int wm = (wid >> 2) * 64;    // warp m-origin within tile
    const int wn = (wid & 3) * 32;     // warp n-origin within tile
    const int m0 = blockIdx.y * BM;
    const int n0 = blockIdx.x * BN;
    const int NC = K / BKC;

    float acc[4][4][4];
    #pragma unroll
    for (int i = 0; i < 4; i++)
        #pragma unroll
        for (int j = 0; j < 4; j++)
            #pragma unroll
            for (int q = 0; q < 4; q++) acc[i][j][q] = 0.f;

    auto load_chunk = [&](int stage, int kc) {
        char* sd = smem + stage * STAGE_BYTES;
        const int k0 = kc * BKC;
        #pragma unroll
        for (int j = 0; j < 8; ++j) {
            const int idx = tid + 256 * j;           // 0..2047
            const int mat = idx >> 9;                // 0..3 (warp-uniform)
            const int rem = idx & 511;
            const int row = rem >> 2;
            const int c16 = rem & 3;
            const uint32_t dst =
                smem_u32(sd + mat * MAT_BYTES + row * ROWB + c16 * 16);
            const int ke = k0 + c16 * 8;
            const bf16* src;
            if (mat == 0)      src = Ahi  + (size_t)(m0 + row) * K + ke;
            else if (mat == 1) src = Alo  + (size_t)(m0 + row) * K + ke;
            else if (mat == 2) src = Bthi + (size_t)(n0 + row) * K + ke;
            else               src = Btlo + (size_t)(n0 + row) * K + ke;
            cp16(dst, src);
        }
    };

    // prologue: chunks 0 .. STAGES-2
    #pragma unroll
    for (int c = 0; c < STAGES - 1; ++c) {
        if (c < NC) load_chunk(c, c);
        cp_commit();
    }

    for (int c = 0; c < NC; ++c) {
        cp_wait<STAGES - 2>();        // chunk c resident
        __syncthreads();              // all warps done with stage (c-1)%S

        const int lc = c + STAGES - 1;
        if (lc < NC) load_chunk(lc % STAGES, lc);
        cp_commit();

        const char* st = smem + (c % STAGES) * STAGE_BYTES;
        #pragma unroll
        for (int k16 = 0; k16 < 2; ++k16) {
            const int xb = k16 * 32;   // 16 elems * 2B
            uint32_t ah[4][4], al[4][4], bh[4][2], bl[4][2];
            #pragma unroll
            for (int mf = 0; mf < 4; ++mf) {
                const int rb = (wm + mf * 16 + gr) * ROWB + xb + gcb;
                ah[mf][0] = lds_u32(st + rb);
                ah[mf][1] = lds_u32(st + rb + 8 * ROWB);
                ah[mf][2] = lds_u32(st + rb + 16);
                ah[mf][3] = lds_u32(st + rb + 8 * ROWB + 16);
                al[mf][0] = lds_u32(st + MAT_BYTES + rb);
                al[mf][1] = lds_u32(st + MAT_BYTES + rb + 8 * ROWB);
                al[mf][2] = lds_u32(st + MAT_BYTES + rb + 16);
                al[mf][3] = lds_u32(st + MAT_BYTES + rb + 8 * ROWB + 16);
            }
            #pragma unroll
            for (int nf = 0; nf < 4; ++nf) {
                const int rb = 2 * MAT_BYTES + (wn + nf * 8 + gr) * ROWB + xb + gcb;
                bh[nf][0] = lds_u32(st + rb);
                bh[nf][1] = lds_u32(st + rb + 16);
                bl[nf][0] = lds_u32(st + MAT_BYTES + rb);
                bl[nf][1] = lds_u32(st + MAT_BYTES + rb + 16);
            }
            #pragma unroll
            for (int mf = 0; mf < 4; ++mf)
                #pragma unroll
                for (int nf = 0; nf < 4; ++nf) {
                    mma_bf16(acc[mf][nf], ah[mf], bh[nf]);
                    mma_bf16(acc[mf][nf], ah[mf], bl[nf]);
                    mma_bf16(acc[mf][nf], al[mf], bh[nf]);
                }
        }
    }

    // epilogue: bias + relu + hi/lo split store
    #pragma unroll
    for (int mf = 0; mf < 4; ++mf) {
        const int r0 = m0 + wm + mf * 16 + gr;
        #pragma unroll
        for (int nf = 0; nf < 4; ++nf) {
            const int c0 = n0 + wn + nf * 8 + (lane & 3) * 2;
            const float bv0 = bias[c0], bv1 = bias[c0 + 1];
            const float v00 = fmaxf(acc[mf][nf][0] + bv0, 0.f);
            const float v01 = fmaxf(acc[mf][nf][1] + bv1, 0.f);
            const float v10 = fmaxf(acc[mf][nf][2] + bv0, 0.f);
            const float v11 = fmaxf(acc[mf][nf][3] + bv1, 0.f);

            bf16 h, l;
            uint32_t hp0, lp0, hp1, lp1;
            split2(v00, h, l);
            hp0 = __bfloat16_as_ushort(h); lp0 = __bfloat16_as_ushort(l);
            split2(v01, h, l);
            hp0 |= (uint32_t)__bfloat16_as_ushort(h) << 16;
            lp0 |= (uint32_t)__bfloat16_as_ushort(l) << 16;
            split2(v10, h, l);
            hp1 = __bfloat16_as_ushort(h); lp1 = __bfloat16_as_ushort(l);
            split2(v11, h, l);
            hp1 |= (uint32_t)__bfloat16_as_ushort(h) << 16;
            lp1 |= (uint32_t)__bfloat16_as_ushort(l) << 16;

            *reinterpret_cast<uint32_t*>(Chi + (size_t)r0 * HID + c0) = hp0;
            *reinterpret_cast<uint32_t*>(Clo + (size_t)r0 * HID + c0) = lp0;
            *reinterpret_cast<uint32_t*>(Chi + (size_t)(r0 + 8) * HID + c0) = hp1;
            *reinterpret_cast<uint32_t*>(Clo + (size_t)(r0 + 8) * HID + c0) = lp1;
        }
    }
}

// ----------------------------------------------------------------------------
// Prep: split x -> padded bf16 hi/lo [N, 128]
// ----------------------------------------------------------------------------
__global__ __launch_bounds__(256) void split_x_kernel(
    const float* __restrict__ x, bf16* __restrict__ hi, bf16* __restrict__ lo)
{
    const size_t idx = (size_t)blockIdx.x * 256 + threadIdx.x;
    const int row = (int)(idx >> 7);
    const int k = (int)(idx & 127);
    float v = (k < FEAT) ? x[(size_t)row * FEAT + k] : 0.f;
    bf16 h, l;
    split2(v, h, l);
    hi[idx] = h;
    lo[idx] = l;
}

// ----------------------------------------------------------------------------
// Prep: W[k,n] -> Wt_hi/lo[n, Kpad] transposed + split, zero padded
// ----------------------------------------------------------------------------
__global__ __launch_bounds__(256) void transpose_split_w_kernel(
    const float* __restrict__ W, int Kin, int Kpad,
    bf16* __restrict__ hi, bf16* __restrict__ lo)
{
    __shared__ float t[32][33];
    const int n0 = blockIdx.x * 32;
    const int k0 = blockIdx.y * 32;
    #pragma unroll
    for (int r = 0; r < 4; ++r) {
        const int k = k0 + threadIdx.y + r * 8;
        t[threadIdx.y + r * 8][threadIdx.x] =
            (k < Kin) ? W[(size_t)k * HID + n0 + threadIdx.x] : 0.f;
    }
    __syncthreads();
    #pragma unroll
    for (int r = 0; r < 4; ++r) {
        const int n = n0 + threadIdx.y + r * 8;
        const int k = k0 + threadIdx.x;
        bf16 h, l;
        split2(t[threadIdx.x][threadIdx.y + r * 8], h, l);
        hi[(size_t)n * Kpad + k] = h;
        lo[(size_t)n * Kpad + k] = l;
    }
}

// ----------------------------------------------------------------------------
// scores[n] = relu( (Hhi+Hlo)[n,:] . W5 + b5 ) ; one warp per row
// ----------------------------------------------------------------------------
__global__ __launch_bounds__(256) void scores_kernel(
    const bf16* __restrict__ Hhi, const bf16* __restrict__ Hlo,
    const float* __restrict__ W5, const float* __restrict__ b5,
    float* __restrict__ scores, int N)
{
    const int gwarp = (blockIdx.x * blockDim.x + threadIdx.x) >> 5;
    const int lane = threadIdx.x & 31;
    if (gwarp >= N) return;
    const bf16* hh = Hhi + (size_t)gwarp * HID;
    const bf16* hl = Hlo + (size_t)gwarp * HID;
    float s = 0.f;
    #pragma unroll 8
    for (int i = lane; i < HID; i += 32) {
        const float h = __bfloat162float(hh[i]) + __bfloat162float(hl[i]);
        s = fmaf(h, W5[i], s);
    }
    #pragma unroll
    for (int o = 16; o > 0; o >>= 1) s += __shfl_xor_sync(0xffffffffu, s, o);
    if (lane == 0) scores[gwarp] = fmaxf(s + b5[0], 0.f);
}

// ----------------------------------------------------------------------------
// Ragged segment softmax + weighted pooling
// ----------------------------------------------------------------------------
__global__ __launch_bounds__(256) void attnpool_kernel(
    const bf16* __restrict__ Hhi, const bf16* __restrict__ Hlo,
    const float* __restrict__ scores, const int* __restrict__ lengths,
    float* __restrict__ pooled)
{
    const int seg = blockIdx.y;
    const int t = threadIdx.x;
    const int d = blockIdx.x * 256 + t;

    int start = 0;
    for (int s = 0; s < seg; s++) start += lengths[s];
    const int len = lengths[seg];

    __shared__ float red[256];

    float m = -INFINITY;
    for (int i = t; i < len; i += 256) m = fmaxf(m, scores[start + i]);
    red[t] = m; __syncthreads();
    #pragma unroll
    for (int o = 128; o > 0; o >>= 1) {
        if (t < o) red[t] = fmaxf(red[t], red[t + o]);
        __syncthreads();
    }
    m = red[0]; __syncthreads();

    float ds = 0.f;
    for (int i = t; i < len; i += 256) ds += __expf(scores[start + i] - m);
    red[t] = ds; __syncthreads();
    #pragma unroll
    for (int o = 128; o > 0; o >>= 1) {
        if (t < o) red[t] += red[t + o];
        __syncthreads();
    }
    const float denom = red[0];

    const bf16* __restrict__ hh = Hhi + (size_t)start * HID + d;
    const bf16* __restrict__ hl = Hlo + (size_t)start * HID + d;
    const float* __restrict__ sp = scores + start;
    float acc = 0.f;
    for (int i = 0; i < len; ++i) {
        const float w = __expf(sp[i] - m);
        const float h = __bfloat162float(hh[(size_t)i * HID]) +
                        __bfloat162float(hl[(size_t)i * HID]);
        acc = fmaf(w, h, acc);
    }
    pooled[seg * HID + d] = acc / denom;
}

// ----------------------------------------------------------------------------
// fp32 SIMT GEMM for the small head (256x1024 @ 1024x1024)
// ----------------------------------------------------------------------------
#define TILE 64
#define KT   16

__global__ __launch_bounds__(256) void gemm_bias_act_kernel(
    const float* __restrict__ A, const float* __restrict__ B,
    const float* __restrict__ bias, float* __restrict__ C,
    int N, int K, int M, int do_relu)
{
    __shared__ float As[KT][TILE + 1];
    __shared__ float Bs[KT][TILE];

    const int tx = threadIdx.x, ty = threadIdx.y;
    const int tid = ty * 16 + tx;
    const int row0 = blockIdx.y * TILE;
    const int col0 = blockIdx.x * TILE;
    const int ar = tid >> 4, ak = tid & 15;
    const int bc = tid & 63, bk = tid >> 6;

    float acc[4][4];
    #pragma unroll
    for (int i = 0; i < 4; i++)
        #pragma unroll
        for (int j = 0; j < 4; j++) acc[i][j] = 0.f;

    for (int k0 = 0; k0 < K; k0 += KT) {
        #pragma unroll
        for (int q = 0; q < 4; q++) {
            const int r = ar + q * 16;
            const int gk = k0 + ak;
            As[ak][r] = (gk < K) ? A[(size_t)(row0 + r) * K + gk] : 0.f;
        }
        #pragma unroll
        for (int q = 0; q < 4; q++) {
            const int kk = bk + q * 4;
            const int gk = k0 + kk;
            Bs[kk][bc] = (gk < K) ? B[(size_t)gk * M + (col0 + bc)] : 0.f;
        }
        __syncthreads();
        #pragma unroll
        for (int kk = 0; kk < KT; kk++) {
            float a[4];
            #pragma unroll
            for (int i = 0; i < 4; i++) a[i] = As[kk][ty * 4 + i];
            const float4 bv = *reinterpret_cast<const float4*>(&Bs[kk][tx * 4]);
            const float b[4] = {bv.x, bv.y, bv.z, bv.w};
            #pragma unroll
            for (int i = 0; i < 4; i++)
                #pragma unroll
                for (int j = 0; j < 4; j++)
                    acc[i][j] = fmaf(a[i], b[j], acc[i][j]);
        }
        __syncthreads();
    }
    #pragma unroll
    for (int i = 0; i < 4; i++) {
        const int r = row0 + ty * 4 + i;
        #pragma unroll
        for (int j = 0; j < 4; j++) {
            const int c = col0 + tx * 4 + j;
            float v = acc[i][j] + bias[c];
            if (do_relu) v = fmaxf(v, 0.f);
            C[(size_t)r * M + c] = v;
        }
    }
}

__global__ void final_kernel(
    const float* __restrict__ T, const float* __restrict__ W7,
    const float* __restrict__ b7, float* __restrict__ out)
{
    const int row = blockIdx.x;
    const int j = threadIdx.y;
    const int lane = threadIdx.x;
    const float* tr = T + (size_t)row * HID;
    float s = 0.f;
    #pragma unroll 8
    for (int k = lane; k < HID; k += 32) s = fmaf(tr[k], W7[k * NCLS + j], s);
    #pragma unroll
    for (int o = 16; o > 0; o >>= 1) s += __shfl_xor_sync(0xffffffffu, s, o);
    if (lane == 0) out[row * NCLS + j] = s + b7[j];
}

// ----------------------------------------------------------------------------
// Launcher
// ----------------------------------------------------------------------------
extern "C" void kernel_launch(void* const* d_in, const int* in_sizes, int n_in,
                              void* d_out, int out_size)
{
    const float* x  = (const float*)d_in[0];
    const float* W1 = (const float*)d_in[1];
    const float* b1 = (const float*)d_in[2];
    const float* W2 = (const float*)d_in[3];
    const float* b2 = (const float*)d_in[4];
    const float* W3 = (const float*)d_in[5];
    const float* b3 = (const float*)d_in[6];
    const float* W4 = (const float*)d_in[7];
    const float* b4 = (const float*)d_in[8];
    const float* W5 = (const float*)d_in[9];
    const float* b5 = (const float*)d_in[10];
    const float* W6 = (const float*)d_in[11];
    const float* b6 = (const float*)d_in[12];
    const float* W7 = (const float*)d_in[13];
    const float* b7 = (const float*)d_in[14];
    const int* lengths = (const int*)d_in[15];
    float* out = (float*)d_out;

    bf16 *xp_hi, *xp_lo, *A_hi, *A_lo, *B_hi, *B_lo, *W1t_hi, *W1t_lo, *Wt_hi, *Wt_lo;
    float *scores, *pooled, *tmp6;
    cudaGetSymbolAddress((void**)&xp_hi, g_xp_hi);
    cudaGetSymbolAddress((void**)&xp_lo, g_xp_lo);
    cudaGetSymbolAddress((void**)&A_hi,  g_A_hi);
    cudaGetSymbolAddress((void**)&A_lo,  g_A_lo);
    cudaGetSymbolAddress((void**)&B_hi,  g_B_hi);
    cudaGetSymbolAddress((void**)&B_lo,  g_B_lo);
    cudaGetSymbolAddress((void**)&W1t_hi, g_W1t_hi);
    cudaGetSymbolAddress((void**)&W1t_lo, g_W1t_lo);
    cudaGetSymbolAddress((void**)&Wt_hi, g_Wt_hi);
    cudaGetSymbolAddress((void**)&Wt_lo, g_Wt_lo);
    cudaGetSymbolAddress((void**)&scores, g_scores);
    cudaGetSymbolAddress((void**)&pooled, g_pooled);
    cudaGetSymbolAddress((void**)&tmp6, g_tmp6);

    cudaFuncSetAttribute(gemm_mma_kernel,
                         cudaFuncAttributeMaxDynamicSharedMemorySize, GEMM_SMEM);

    // prep
    split_x_kernel<<<(TOTAL_N * K1P) / 256, 256>>>(x, xp_hi, xp_lo);
    transpose_split_w_kernel<<<dim3(HID / 32, K1P / 32), dim3(32, 8)>>>(
        W1, FEAT, K1P, W1t_hi, W1t_lo);
    transpose_split_w_kernel<<<dim3(HID / 32, HID / 32), dim3(32, 8)>>>(
        W2, HID, HID, Wt_hi + 0 * HID * HID, Wt_lo + 0 * HID * HID);
    transpose_split_w_kernel<<<dim3(HID / 32, HID / 32), dim3(32, 8)>>>(
        W3, HID, HID, Wt_hi + 1 * HID * HID, Wt_lo + 1 * HID * HID);
    transpose_split_w_kernel<<<dim3(HID / 32, HID / 32), dim3(32, 8)>>>(
        W4, HID, HID, Wt_hi + 2 * HID * HID, Wt_lo + 2 * HID * HID);

    const dim3 gemm_grid(HID / BN, TOTAL_N / BM);   // (8, 1024)

    gemm_mma_kernel<<<gemm_grid, 256, GEMM_SMEM>>>(
        xp_hi, xp_lo, W1t_hi, W1t_lo, b1, A_hi, A_lo, K1P);
    gemm_mma_kernel<<<gemm_grid, 256, GEMM_SMEM>>>(
        A_hi, A_lo, Wt_hi + 0 * HID * HID, Wt_lo + 0 * HID * HID, b2,
        B_hi, B_lo, HID);
    gemm_mma_kernel<<<gemm_grid, 256, GEMM_SMEM>>>(
        B_hi, B_lo, Wt_hi + 1 * HID * HID, Wt_lo + 1 * HID * HID, b3,
        A_hi, A_lo, HID);
    gemm_mma_kernel<<<gemm_grid, 256, GEMM_SMEM>>>(
        A_hi, A_lo, Wt_hi + 2 * HID * HID, Wt_lo + 2 * HID * HID, b4,
        B_hi, B_lo, HID);

    scores_kernel<<<(TOTAL_N * 32 + 255) / 256, 256>>>(
        B_hi, B_lo, W5, b5, scores, TOTAL_N);
    attnpool_kernel<<<dim3(HID / 256, NSEG), 256>>>(
        B_hi, B_lo, scores, lengths, pooled);

    gemm_bias_act_kernel<<<dim3(HID / TILE, NSEG / TILE), dim3(16, 16)>>>(
        pooled, W6, b6, tmp6, NSEG, HID, HID, 1);
    final_kernel<<<NSEG, dim3(32, NCLS)>>>(tmp6, W7, b7, out);

    (void)in_sizes; (void)n_in; (void)out_size;
}

// round 4
// speedup vs baseline: 4.2286x; 1.6367x over previous
#include <cuda_runtime.h>
#include <cuda_fp16.h>
#include <math.h>
#include <stdint.h>

// ----------------------------------------------------------------------------
// Dnn_with_Attention on sm_103 (family-generic: mma.sync HMMA path).
// fp16 A-split scheme: activations stored as fp16 hi+lo (exact ~2^-22),
// weights single fp16 -> 2 MMAs per output element, fp32 accumulate.
// ldmatrix.x4 fragment loads; cp.async 3-stage pipeline.
// W5 attention-logit GEMV fused into layer-4 epilogue.
// ----------------------------------------------------------------------------

#define TOTAL_N 131072
#define HID     1024
#define FEAT    78
#define K1P     128
#define NSEG    256
#define NCLS    10

#define BM 128
#define BN 128
#define BKC 32                       // K elems per chunk
#define STAGES 3
#define ROWB 80                      // 32 fp16 = 64B + 16B pad
#define MAT_BYTES (128 * ROWB)       // 10240
#define STAGE_BYTES (3 * MAT_BYTES)  // A_hi, A_lo, B
#define GEMM_SMEM (STAGES * STAGE_BYTES)   // 92160

typedef __half f16;

// ------------------------------- scratch -----------------------------------
__device__ f16 g_xp_hi[(size_t)TOTAL_N * K1P];
__device__ f16 g_xp_lo[(size_t)TOTAL_N * K1P];
__device__ f16 g_A_hi[(size_t)TOTAL_N * HID];
__device__ f16 g_A_lo[(size_t)TOTAL_N * HID];
__device__ f16 g_B_hi[(size_t)TOTAL_N * HID];
__device__ f16 g_B_lo[(size_t)TOTAL_N * HID];
__device__ f16 g_W1t[HID * K1P];
__device__ f16 g_Wt[3][HID * HID];
__device__ float g_scores_raw[TOTAL_N];
__device__ float g_pooled[NSEG * HID];
__device__ float g_tmp6[NSEG * HID];

// ------------------------------ helpers ------------------------------------
__device__ __forceinline__ uint32_t smem_u32(const void* p) {
    uint32_t a;
    asm("{ .reg .u64 t; cvta.to.shared.u64 t, %1; cvt.u32.u64 %0, t; }"
        : "=r"(a) : "l"(p));
    return a;
}
__device__ __forceinline__ void cp16(uint32_t dst, const void* src) {
    asm volatile("cp.async.cg.shared.global [%0], [%1], 16;"
                 :: "r"(dst), "l"(src) : "memory");
}
__device__ __forceinline__ void cp_commit() {
    asm volatile("cp.async.commit_group;" ::: "memory");
}
template <int N>
__device__ __forceinline__ void cp_wait() {
    asm volatile("cp.async.wait_group %0;" :: "n"(N) : "memory");
}
__device__ __forceinline__ void ldmx4(uint32_t* r, uint32_t addr) {
    asm volatile("ldmatrix.sync.aligned.m8n8.x4.shared.b16 {%0,%1,%2,%3}, [%4];"
                 : "=r"(r[0]), "=r"(r[1]), "=r"(r[2]), "=r"(r[3]) : "r"(addr));
}
__device__ __forceinline__ void mma_f16(float* c, const uint32_t* a,
                                        const uint32_t* b) {
    asm volatile(
        "mma.sync.aligned.m16n8k16.row.col.f32.f16.f16.f32 "
        "{%0,%1,%2,%3}, {%4,%5,%6,%7}, {%8,%9}, {%0,%1,%2,%3};"
        : "+f"(c[0]), "+f"(c[1]), "+f"(c[2]), "+f"(c[3])
        : "r"(a[0]), "r"(a[1]), "r"(a[2]), "r"(a[3]), "r"(b[0]), "r"(b[1]));
}
__device__ __forceinline__ void split2h(float v, f16& h, f16& l) {
    h = __float2half(v);
    l = __float2half(v - __half2float(h));
}

// ----------------------------------------------------------------------------
// HMMA GEMM: C[M,1024] = relu(A[M,K] @ Bt[1024,K]^T + bias)
//   A = Ahi + Alo (fp16 pair), Bt single fp16. 2 MMAs per tile.
// Optional fused W5 partial dots -> atomicAdd(scores_raw) (layer 4).
// grid = (1024/BN, M/BM), block = 256 (8 warps, each 64x32).
// ----------------------------------------------------------------------------
__global__ void __launch_bounds__(256) gemm_mma_kernel(
    const f16* __restrict__ Ahi, const f16* __restrict__ Alo,
    const f16* __restrict__ Bt, const float* __restrict__ bias,
    f16* __restrict__ Chi, f16* __restrict__ Clo,
    const float* __restrict__ W5, float* __restrict__ scores_raw,
    int K)
{
    extern __shared__ char smem[];
    const uint32_t sbase = smem_u32(smem);
    const int tid = threadIdx.x;
    const int lane = tid & 31;
    const int wid = tid >> 5;
    const int wm = (wid >> 2) * 64;    // warp m-origin in tile
    const int wn = (wid & 3) * 32;     // warp n-origin in tile
    const int m0 = blockIdx.y * BM;
    const int n0 = blockIdx.x * BN;
    const int NC = K / BKC;

    // ldmatrix lane-address components (byte offsets within a matrix tile)
    const int a_row = lane & 15;            // + wm + mf*16
    const int a_kb  = (lane >> 4) * 16;     // 0 or 16 bytes (k 0-7 / 8-15)
    const int b_row = (lane & 7) + 8 * (lane >> 4);   // + wn + p*16
    const int b_kb  = ((lane >> 3) & 1) * 16;

    float acc[4][4][4];
    #pragma unroll
    for (int i = 0; i < 4; i++)
        #pragma unroll
        for (int j = 0; j < 4; j++)
            #pragma unroll
            for (int q = 0; q < 4; q++) acc[i][j][q] = 0.f;

    auto load_chunk = [&](int stage, int kc) {
        const uint32_t sd = sbase + stage * STAGE_BYTES;
        const int k0 = kc * BKC;
        #pragma unroll
        for (int j = 0; j < 6; ++j) {
            const int idx = tid + 256 * j;           // 0..1535
            const int mat = idx >> 9;                // 0..2
            const int rem = idx & 511;
            const int row = rem >> 2;
            const int c16 = rem & 3;
            const uint32_t dst = sd + mat * MAT_BYTES + row * ROWB + c16 * 16;
            const int ke = k0 + c16 * 8;
            const f16* src;
            if (mat == 0)      src = Ahi + (size_t)(m0 + row) * K + ke;
            else if (mat == 1) src = Alo + (size_t)(m0 + row) * K + ke;
            else               src = Bt  + (size_t)(n0 + row) * K + ke;
            cp16(dst, src);
        }
    };

    #pragma unroll
    for (int c = 0; c < STAGES - 1; ++c) {
        if (c < NC) load_chunk(c, c);
        cp_commit();
    }

    for (int c = 0; c < NC; ++c) {
        cp_wait<STAGES - 2>();
        __syncthreads();

        const int lc = c + STAGES - 1;
        if (lc < NC) load_chunk(lc % STAGES, lc);
        cp_commit();

        const uint32_t st = sbase + (c % STAGES) * STAGE_BYTES;
        #pragma unroll
        for (int k16 = 0; k16 < 2; ++k16) {
            const int xb = k16 * 32;   // 16 elems * 2B
            uint32_t ah[4][4], al[4][4], b[4][2];
            #pragma unroll
            for (int mf = 0; mf < 4; ++mf) {
                const uint32_t ra =
                    st + (wm + mf * 16 + a_row) * ROWB + xb + a_kb;
                ldmx4(ah[mf], ra);
                ldmx4(al[mf], ra + MAT_BYTES);
            }
            #pragma unroll
            for (int p = 0; p < 2; ++p) {
                uint32_t r[4];
                ldmx4(r, st + 2 * MAT_BYTES +
                          (wn + p * 16 + b_row) * ROWB + xb + b_kb);
                b[p * 2][0] = r[0]; b[p * 2][1] = r[1];
                b[p * 2 + 1][0] = r[2]; b[p * 2 + 1][1] = r[3];
            }
            #pragma unroll
            for (int mf = 0; mf < 4; ++mf)
                #pragma unroll
                for (int nf = 0; nf < 4; ++nf) {
                    mma_f16(acc[mf][nf], ah[mf], b[nf]);
                    mma_f16(acc[mf][nf], al[mf], b[nf]);
                }
        }
    }

    // epilogue: bias + relu + fp16 hi/lo split store (+ fused W5 dot)
    const int gr = lane >> 2;
    float sdot[4][2];
    #pragma unroll
    for (int mf = 0; mf < 4; ++mf) { sdot[mf][0] = 0.f; sdot[mf][1] = 0.f; }

    #pragma unroll
    for (int mf = 0; mf < 4; ++mf) {
        const int r0 = m0 + wm + mf * 16 + gr;
        #pragma unroll
        for (int nf = 0; nf < 4; ++nf) {
            const int c0 = n0 + wn + nf * 8 + (lane & 3) * 2;
            const float bv0 = bias[c0], bv1 = bias[c0 + 1];
            const float v00 = fmaxf(acc[mf][nf][0] + bv0, 0.f);
            const float v01 = fmaxf(acc[mf][nf][1] + bv1, 0.f);
            const float v10 = fmaxf(acc[mf][nf][2] + bv0, 0.f);
            const float v11 = fmaxf(acc[mf][nf][3] + bv1, 0.f);

            if (W5 != nullptr) {
                const float w0 = W5[c0], w1 = W5[c0 + 1];
                sdot[mf][0] = fmaf(v00, w0, fmaf(v01, w1, sdot[mf][0]));
                sdot[mf][1] = fmaf(v10, w0, fmaf(v11, w1, sdot[mf][1]));
            }

            f16 h, l;
            uint32_t hp0, lp0, hp1, lp1;
            split2h(v00, h, l);
            hp0 = __half_as_ushort(h); lp0 = __half_as_ushort(l);
            split2h(v01, h, l);
            hp0 |= (uint32_t)__half_as_ushort(h) << 16;
            lp0 |= (uint32_t)__half_as_ushort(l) << 16;
            split2h(v10, h, l);
            hp1 = __half_as_ushort(h); lp1 = __half_as_ushort(l);
            split2h(v11, h, l);
            hp1 |= (uint32_t)__half_as_ushort(h) << 16;
            lp1 |= (uint32_t)__half_as_ushort(l) << 16;

            *reinterpret_cast<uint32_t*>(Chi + (size_t)r0 * HID + c0) = hp0;
            *reinterpret_cast<uint32_t*>(Clo + (size_t)r0 * HID + c0) = lp0;
            *reinterpret_cast<uint32_t*>(Chi + (size_t)(r0 + 8) * HID + c0) = hp1;
            *reinterpret_cast<uint32_t*>(Clo + (size_t)(r0 + 8) * HID + c0) = lp1;
        }
    }

    if (W5 != nullptr) {
        #pragma unroll
        for (int mf = 0; mf < 4; ++mf) {
            float s0 = sdot[mf][0], s1 = sdot[mf][1];
            s0 += __shfl_xor_sync(0xffffffffu, s0, 1);
            s0 += __shfl_xor_sync(0xffffffffu, s0, 2);
            s1 += __shfl_xor_sync(0xffffffffu, s1, 1);
            s1 += __shfl_xor_sync(0xffffffffu, s1, 2);
            if ((lane & 3) == 0) {
                const int r0 = m0 + wm + mf * 16 + gr;
                atomicAdd(&scores_raw[r0], s0);
                atomicAdd(&scores_raw[r0 + 8], s1);
            }
        }
    }
}

// ----------------------------------------------------------------------------
// Prep kernels
// ----------------------------------------------------------------------------
__global__ __launch_bounds__(256) void split_x_kernel(
    const float* __restrict__ x, f16* __restrict__ hi, f16* __restrict__ lo)
{
    const size_t idx = (size_t)blockIdx.x * 256 + threadIdx.x;
    const int row = (int)(idx >> 7);
    const int k = (int)(idx & 127);
    float v = (k < FEAT) ? x[(size_t)row * FEAT + k] : 0.f;
    f16 h, l;
    split2h(v, h, l);
    hi[idx] = h;
    lo[idx] = l;
}

__global__ __launch_bounds__(256) void transpose_w_kernel(
    const float* __restrict__ W, int Kin, int Kpad, f16* __restrict__ Wt)
{
    __shared__ float t[32][33];
    const int n0 = blockIdx.x * 32;
    const int k0 = blockIdx.y * 32;
    #pragma unroll
    for (int r = 0; r < 4; ++r) {
        const int k = k0 + threadIdx.y + r * 8;
        t[threadIdx.y + r * 8][threadIdx.x] =
            (k < Kin) ? W[(size_t)k * HID + n0 + threadIdx.x] : 0.f;
    }
    __syncthreads();
    #pragma unroll
    for (int r = 0; r < 4; ++r) {
        const int n = n0 + threadIdx.y + r * 8;
        const int k = k0 + threadIdx.x;
        Wt[(size_t)n * Kpad + k] = __float2half(t[threadIdx.x][threadIdx.y + r * 8]);
    }
}

__global__ __launch_bounds__(256) void zero_kernel(float* __restrict__ p, int n)
{
    const int i = blockIdx.x * 256 + threadIdx.x;
    if (i < n) p[i] = 0.f;
}

// ----------------------------------------------------------------------------
// Ragged segment softmax + weighted pooling. score_i = relu(raw_i + b5).
// ----------------------------------------------------------------------------
__global__ __launch_bounds__(256) void attnpool_kernel(
    const f16* __restrict__ Hhi, const f16* __restrict__ Hlo,
    const float* __restrict__ raw, const float* __restrict__ b5,
    const int* __restrict__ lengths, float* __restrict__ pooled)
{
    const int seg = blockIdx.y;
    const int t = threadIdx.x;
    const int d = blockIdx.x * 256 + t;
    const float b5v = b5[0];

    int start = 0;
    for (int s = 0; s < seg; s++) start += lengths[s];
    const int len = lengths[seg];

    __shared__ float red[256];

    float m = -INFINITY;
    for (int i = t; i < len; i += 256)
        m = fmaxf(m, fmaxf(raw[start + i] + b5v, 0.f));
    red[t] = m; __syncthreads();
    #pragma unroll
    for (int o = 128; o > 0; o >>= 1) {
        if (t < o) red[t] = fmaxf(red[t], red[t + o]);
        __syncthreads();
    }
    m = red[0]; __syncthreads();

    float ds = 0.f;
    for (int i = t; i < len; i += 256)
        ds += __expf(fmaxf(raw[start + i] + b5v, 0.f) - m);
    red[t] = ds; __syncthreads();
    #pragma unroll
    for (int o = 128; o > 0; o >>= 1) {
        if (t < o) red[t] += red[t + o];
        __syncthreads();
    }
    const float denom = red[0];

    const f16* __restrict__ hh = Hhi + (size_t)start * HID + d;
    const f16* __restrict__ hl = Hlo + (size_t)start * HID + d;
    const float* __restrict__ sp = raw + start;
    float acc = 0.f;
    for (int i = 0; i < len; ++i) {
        const float w = __expf(fmaxf(sp[i] + b5v, 0.f) - m);
        const float h = __half2float(hh[(size_t)i * HID]) +
                        __half2float(hl[(size_t)i * HID]);
        acc = fmaf(w, h, acc);
    }
    pooled[seg * HID + d] = acc / denom;
}

// ----------------------------------------------------------------------------
// fp32 SIMT GEMM for the small head (256x1024 @ 1024x1024)
// ----------------------------------------------------------------------------
#define TILE 64
#define KT   16

__global__ __launch_bounds__(256) void gemm_bias_act_kernel(
    const float* __restrict__ A, const float* __restrict__ B,
    const float* __restrict__ bias, float* __restrict__ C,
    int N, int K, int M, int do_relu)
{
    __shared__ float As[KT][TILE + 1];
    __shared__ float Bs[KT][TILE];

    const int tx = threadIdx.x, ty = threadIdx.y;
    const int tid = ty * 16 + tx;
    const int row0 = blockIdx.y * TILE;
    const int col0 = blockIdx.x * TILE;
    const int ar = tid >> 4, ak = tid & 15;
    const int bc = tid & 63, bk = tid >> 6;

    float acc[4][4];
    #pragma unroll
    for (int i = 0; i < 4; i++)
        #pragma unroll
        for (int j = 0; j < 4; j++) acc[i][j] = 0.f;

    for (int k0 = 0; k0 < K; k0 += KT) {
        #pragma unroll
        for (int q = 0; q < 4; q++) {
            const int r = ar + q * 16;
            const int gk = k0 + ak;
            As[ak][r] = (gk < K) ? A[(size_t)(row0 + r) * K + gk] : 0.f;
        }
        #pragma unroll
        for (int q = 0; q < 4; q++) {
            const int kk = bk + q * 4;
            const int gk = k0 + kk;
            Bs[kk][bc] = (gk < K) ? B[(size_t)gk * M + (col0 + bc)] : 0.f;
        }
        __syncthreads();
        #pragma unroll
        for (int kk = 0; kk < KT; kk++) {
            float a[4];
            #pragma unroll
            for (int i = 0; i < 4; i++) a[i] = As[kk][ty * 4 + i];
            const float4 bv = *reinterpret_cast<const float4*>(&Bs[kk][tx * 4]);
            const float b[4] = {bv.x, bv.y, bv.z, bv.w};
            #pragma unroll
            for (int i = 0; i < 4; i++)
                #pragma unroll
                for (int j = 0; j < 4; j++)
                    acc[i][j] = fmaf(a[i], b[j], acc[i][j]);
        }
        __syncthreads();
    }
    #pragma unroll
    for (int i = 0; i < 4; i++) {
        const int r = row0 + ty * 4 + i;
        #pragma unroll
        for (int j = 0; j < 4; j++) {
            const int c = col0 + tx * 4 + j;
            float v = acc[i][j] + bias[c];
            if (do_relu) v = fmaxf(v, 0.f);
            C[(size_t)r * M + c] = v;
        }
    }
}

__global__ void final_kernel(
    const float* __restrict__ T, const float* __restrict__ W7,
    const float* __restrict__ b7, float* __restrict__ out)
{
    const int row = blockIdx.x;
    const int j = threadIdx.y;
    const int lane = threadIdx.x;
    const float* tr = T + (size_t)row * HID;
    float s = 0.f;
    #pragma unroll 8
    for (int k = lane; k < HID; k += 32) s = fmaf(tr[k], W7[k * NCLS + j], s);
    #pragma unroll
    for (int o = 16; o > 0; o >>= 1) s += __shfl_xor_sync(0xffffffffu, s, o);
    if (lane == 0) out[row * NCLS + j] = s + b7[j];
}

// ----------------------------------------------------------------------------
// Launcher
// ----------------------------------------------------------------------------
extern "C" void kernel_launch(void* const* d_in, const int* in_sizes, int n_in,
                              void* d_out, int out_size)
{
    const float* x  = (const float*)d_in[0];
    const float* W1 = (const float*)d_in[1];
    const float* b1 = (const float*)d_in[2];
    const float* W2 = (const float*)d_in[3];
    const float* b2 = (const float*)d_in[4];
    const float* W3 = (const float*)d_in[5];
    const float* b3 = (const float*)d_in[6];
    const float* W4 = (const float*)d_in[7];
    const float* b4 = (const float*)d_in[8];
    const float* W5 = (const float*)d_in[9];
    const float* b5 = (const float*)d_in[10];
    const float* W6 = (const float*)d_in[11];
    const float* b6 = (const float*)d_in[12];
    const float* W7 = (const float*)d_in[13];
    const float* b7 = (const float*)d_in[14];
    const int* lengths = (const int*)d_in[15];
    float* out = (float*)d_out;

    f16 *xp_hi, *xp_lo, *A_hi, *A_lo, *B_hi, *B_lo, *W1t, *Wt;
    float *scores_raw, *pooled, *tmp6;
    cudaGetSymbolAddress((void**)&xp_hi, g_xp_hi);
    cudaGetSymbolAddress((void**)&xp_lo, g_xp_lo);
    cudaGetSymbolAddress((void**)&A_hi,  g_A_hi);
    cudaGetSymbolAddress((void**)&A_lo,  g_A_lo);
    cudaGetSymbolAddress((void**)&B_hi,  g_B_hi);
    cudaGetSymbolAddress((void**)&B_lo,  g_B_lo);
    cudaGetSymbolAddress((void**)&W1t, g_W1t);
    cudaGetSymbolAddress((void**)&Wt, g_Wt);
    cudaGetSymbolAddress((void**)&scores_raw, g_scores_raw);
    cudaGetSymbolAddress((void**)&pooled, g_pooled);
    cudaGetSymbolAddress((void**)&tmp6, g_tmp6);

    cudaFuncSetAttribute(gemm_mma_kernel,
                         cudaFuncAttributeMaxDynamicSharedMemorySize, GEMM_SMEM);

    // prep
    split_x_kernel<<<(TOTAL_N * K1P) / 256, 256>>>(x, xp_hi, xp_lo);
    transpose_w_kernel<<<dim3(HID / 32, K1P / 32), dim3(32, 8)>>>(
        W1, FEAT, K1P, W1t);
    transpose_w_kernel<<<dim3(HID / 32, HID / 32), dim3(32, 8)>>>(
        W2, HID, HID, Wt + 0 * HID * HID);
    transpose_w_kernel<<<dim3(HID / 32, HID / 32), dim3(32, 8)>>>(
        W3, HID, HID, Wt + 1 * HID * HID);
    transpose_w_kernel<<<dim3(HID / 32, HID / 32), dim3(32, 8)>>>(
        W4, HID, HID, Wt + 2 * HID * HID);
    zero_kernel<<<TOTAL_N / 256, 256>>>(scores_raw, TOTAL_N);

    const dim3 gemm_grid(HID / BN, TOTAL_N / BM);   // (8, 1024)

    gemm_mma_kernel<<<gemm_grid, 256, GEMM_SMEM>>>(
        xp_hi, xp_lo, W1t, b1, A_hi, A_lo, nullptr, nullptr, K1P);
    gemm_mma_kernel<<<gemm_grid, 256, GEMM_SMEM>>>(
        A_hi, A_lo, Wt + 0 * HID * HID, b2, B_hi, B_lo, nullptr, nullptr, HID);
    gemm_mma_kernel<<<gemm_grid, 256, GEMM_SMEM>>>(
        B_hi, B_lo, Wt + 1 * HID * HID, b3, A_hi, A_lo, nullptr, nullptr, HID);
    gemm_mma_kernel<<<gemm_grid, 256, GEMM_SMEM>>>(
        A_hi, A_lo, Wt + 2 * HID * HID, b4, B_hi, B_lo, W5, scores_raw, HID);

    attnpool_kernel<<<dim3(HID / 256, NSEG), 256>>>(
        B_hi, B_lo, scores_raw, b5, lengths, pooled);

    gemm_bias_act_kernel<<<dim3(HID / TILE, NSEG / TILE), dim3(16, 16)>>>(
        pooled, W6, b6, tmp6, NSEG, HID, HID, 1);
    final_kernel<<<NSEG, dim3(32, NCLS)>>>(tmp6, W7, b7, out);

    (void)in_sizes; (void)n_in; (void)out_size;
}

// round 5
// speedup vs baseline: 6.9952x; 1.6543x over previous
#include <cuda_runtime.h>
#include <cuda_fp16.h>
#include <math.h>
#include <stdint.h>

// ----------------------------------------------------------------------------
// Dnn_with_Attention on sm_103 (family-generic: mma.sync HMMA path).
// Pure fp16 operands (weights + activations), fp32 accumulate, 1 MMA/element.
// 128x256 CTA tile, 512 threads, ldmatrix.x4, cp.async 3-stage pipeline.
// W5 attention-logit GEMV fused into layer-4 epilogue.
// ----------------------------------------------------------------------------

#define TOTAL_N 131072
#define HID     1024
#define FEAT    78
#define K1P     128
#define NSEG    256
#define NCLS    10

#define BM 128
#define BN 256
#define BKC 32                        // K elems per chunk
#define STAGES 3
#define ROWB 80                       // 32 fp16 = 64B + 16B pad
#define A_BYTES (BM * ROWB)           // 10240
#define B_BYTES (BN * ROWB)           // 20480
#define STAGE_BYTES (A_BYTES + B_BYTES)        // 30720
#define GEMM_SMEM (STAGES * STAGE_BYTES)       // 92160

typedef __half f16;

// ------------------------------- scratch -----------------------------------
__device__ f16 g_xp[(size_t)TOTAL_N * K1P];
__device__ f16 g_A[(size_t)TOTAL_N * HID];
__device__ f16 g_B[(size_t)TOTAL_N * HID];
__device__ f16 g_W1t[HID * K1P];
__device__ f16 g_Wt[3][HID * HID];
__device__ float g_scores_raw[TOTAL_N];
__device__ float g_pooled[NSEG * HID];
__device__ float g_tmp6[NSEG * HID];

// ------------------------------ helpers ------------------------------------
__device__ __forceinline__ uint32_t smem_u32(const void* p) {
    uint32_t a;
    asm("{ .reg .u64 t; cvta.to.shared.u64 t, %1; cvt.u32.u64 %0, t; }"
        : "=r"(a) : "l"(p));
    return a;
}
__device__ __forceinline__ void cp16(uint32_t dst, const void* src) {
    asm volatile("cp.async.cg.shared.global [%0], [%1], 16;"
                 :: "r"(dst), "l"(src) : "memory");
}
__device__ __forceinline__ void cp_commit() {
    asm volatile("cp.async.commit_group;" ::: "memory");
}
template <int N>
__device__ __forceinline__ void cp_wait() {
    asm volatile("cp.async.wait_group %0;" :: "n"(N) : "memory");
}
__device__ __forceinline__ void ldmx4(uint32_t* r, uint32_t addr) {
    asm volatile("ldmatrix.sync.aligned.m8n8.x4.shared.b16 {%0,%1,%2,%3}, [%4];"
                 : "=r"(r[0]), "=r"(r[1]), "=r"(r[2]), "=r"(r[3]) : "r"(addr));
}
__device__ __forceinline__ void mma_f16(float* c, const uint32_t* a,
                                        const uint32_t* b) {
    asm volatile(
        "mma.sync.aligned.m16n8k16.row.col.f32.f16.f16.f32 "
        "{%0,%1,%2,%3}, {%4,%5,%6,%7}, {%8,%9}, {%0,%1,%2,%3};"
        : "+f"(c[0]), "+f"(c[1]), "+f"(c[2]), "+f"(c[3])
        : "r"(a[0]), "r"(a[1]), "r"(a[2]), "r"(a[3]), "r"(b[0]), "r"(b[1]));
}

// ----------------------------------------------------------------------------
// HMMA GEMM: C[M,1024] = relu(A[M,K] @ Bt[1024,K]^T + bias), all fp16 in,
// fp32 accumulate. Optional fused W5 dots -> atomicAdd(scores_raw) (layer 4).
// grid = (1024/BN, M/BM), block = 512 (16 warps, each 32x64).
// ----------------------------------------------------------------------------
__global__ void __launch_bounds__(512) gemm_mma_kernel(
    const f16* __restrict__ A, const f16* __restrict__ Bt,
    const float* __restrict__ bias, f16* __restrict__ C,
    const float* __restrict__ W5, float* __restrict__ scores_raw,
    int K)
{
    extern __shared__ char smem[];
    const uint32_t sbase = smem_u32(smem);
    const int tid = threadIdx.x;
    const int lane = tid & 31;
    const int wid = tid >> 5;
    const int wm = (wid & 3) * 32;     // warp m-origin (4 x 32 = 128)
    const int wn = (wid >> 2) * 64;    // warp n-origin (4 x 64 = 256)
    const int m0 = blockIdx.y * BM;
    const int n0 = blockIdx.x * BN;
    const int NC = K / BKC;

    // ldmatrix lane-address components
    const int a_row = lane & 15;
    const int a_kb  = (lane >> 4) * 16;
    const int b_row = (lane & 7) + 8 * (lane >> 4);
    const int b_kb  = ((lane >> 3) & 1) * 16;

    float acc[2][8][4];
    #pragma unroll
    for (int i = 0; i < 2; i++)
        #pragma unroll
        for (int j = 0; j < 8; j++)
            #pragma unroll
            for (int q = 0; q < 4; q++) acc[i][j][q] = 0.f;

    auto load_chunk = [&](int stage, int kc) {
        const uint32_t sd = sbase + stage * STAGE_BYTES;
        const int k0 = kc * BKC;
        // A tile: 512 x 16B transfers (tid covers it exactly once)
        {
            const int row = tid >> 2;
            const int c16 = tid & 3;
            cp16(sd + row * ROWB + c16 * 16,
                 A + (size_t)(m0 + row) * K + k0 + c16 * 8);
        }
        // B tile: 1024 x 16B transfers (2 per thread)
        #pragma unroll
        for (int j = 0; j < 2; ++j) {
            const int idx = tid + 512 * j;
            const int row = idx >> 2;
            const int c16 = idx & 3;
            cp16(sd + A_BYTES + row * ROWB + c16 * 16,
                 Bt + (size_t)(n0 + row) * K + k0 + c16 * 8);
        }
    };

    #pragma unroll
    for (int c = 0; c < STAGES - 1; ++c) {
        if (c < NC) load_chunk(c, c);
        cp_commit();
    }

    for (int c = 0; c < NC; ++c) {
        cp_wait<STAGES - 2>();
        __syncthreads();

        const int lc = c + STAGES - 1;
        if (lc < NC) load_chunk(lc % STAGES, lc);
        cp_commit();

        const uint32_t st = sbase + (c % STAGES) * STAGE_BYTES;
        #pragma unroll
        for (int k16 = 0; k16 < 2; ++k16) {
            const int xb = k16 * 32;
            uint32_t a[2][4], b[8][2];
            #pragma unroll
            for (int mf = 0; mf < 2; ++mf)
                ldmx4(a[mf], st + (wm + mf * 16 + a_row) * ROWB + xb + a_kb);
            #pragma unroll
            for (int p = 0; p < 4; ++p) {
                uint32_t r[4];
                ldmx4(r, st + A_BYTES +
                          (wn + p * 16 + b_row) * ROWB + xb + b_kb);
                b[p * 2][0] = r[0]; b[p * 2][1] = r[1];
                b[p * 2 + 1][0] = r[2]; b[p * 2 + 1][1] = r[3];
            }
            #pragma unroll
            for (int mf = 0; mf < 2; ++mf)
                #pragma unroll
                for (int nf = 0; nf < 8; ++nf)
                    mma_f16(acc[mf][nf], a[mf], b[nf]);
        }
    }

    // epilogue: bias + relu + fp16 store (+ fused W5 dot)
    const int gr = lane >> 2;
    float sdot[2][2];
    sdot[0][0] = sdot[0][1] = sdot[1][0] = sdot[1][1] = 0.f;

    #pragma unroll
    for (int mf = 0; mf < 2; ++mf) {
        const int r0 = m0 + wm + mf * 16 + gr;
        #pragma unroll
        for (int nf = 0; nf < 8; ++nf) {
            const int c0 = n0 + wn + nf * 8 + (lane & 3) * 2;
            const float bv0 = bias[c0], bv1 = bias[c0 + 1];
            const float v00 = fmaxf(acc[mf][nf][0] + bv0, 0.f);
            const float v01 = fmaxf(acc[mf][nf][1] + bv1, 0.f);
            const float v10 = fmaxf(acc[mf][nf][2] + bv0, 0.f);
            const float v11 = fmaxf(acc[mf][nf][3] + bv1, 0.f);

            if (W5 != nullptr) {
                const float w0 = W5[c0], w1 = W5[c0 + 1];
                sdot[mf][0] = fmaf(v00, w0, fmaf(v01, w1, sdot[mf][0]));
                sdot[mf][1] = fmaf(v10, w0, fmaf(v11, w1, sdot[mf][1]));
            }

            const uint32_t p0 =
                ((uint32_t)__half_as_ushort(__float2half(v01)) << 16) |
                __half_as_ushort(__float2half(v00));
            const uint32_t p1 =
                ((uint32_t)__half_as_ushort(__float2half(v11)) << 16) |
                __half_as_ushort(__float2half(v10));
            *reinterpret_cast<uint32_t*>(C + (size_t)r0 * HID + c0) = p0;
            *reinterpret_cast<uint32_t*>(C + (size_t)(r0 + 8) * HID + c0) = p1;
        }
    }

    if (W5 != nullptr) {
        #pragma unroll
        for (int mf = 0; mf < 2; ++mf) {
            float s0 = sdot[mf][0], s1 = sdot[mf][1];
            s0 += __shfl_xor_sync(0xffffffffu, s0, 1);
            s0 += __shfl_xor_sync(0xffffffffu, s0, 2);
            s1 += __shfl_xor_sync(0xffffffffu, s1, 1);
            s1 += __shfl_xor_sync(0xffffffffu, s1, 2);
            if ((lane & 3) == 0) {
                const int r0 = m0 + wm + mf * 16 + gr;
                atomicAdd(&scores_raw[r0], s0);
                atomicAdd(&scores_raw[r0 + 8], s1);
            }
        }
    }
}

// ----------------------------------------------------------------------------
// Prep kernels
// ----------------------------------------------------------------------------
__global__ __launch_bounds__(256) void convert_x_kernel(
    const float* __restrict__ x, f16* __restrict__ xp)
{
    const size_t idx = (size_t)blockIdx.x * 256 + threadIdx.x;
    const int row = (int)(idx >> 7);
    const int k = (int)(idx & 127);
    xp[idx] = __float2half((k < FEAT) ? x[(size_t)row * FEAT + k] : 0.f);
}

__global__ __launch_bounds__(256) void transpose_w_kernel(
    const float* __restrict__ W, int Kin, int Kpad, f16* __restrict__ Wt)
{
    __shared__ float t[32][33];
    const int n0 = blockIdx.x * 32;
    const int k0 = blockIdx.y * 32;
    #pragma unroll
    for (int r = 0; r < 4; ++r) {
        const int k = k0 + threadIdx.y + r * 8;
        t[threadIdx.y + r * 8][threadIdx.x] =
            (k < Kin) ? W[(size_t)k * HID + n0 + threadIdx.x] : 0.f;
    }
    __syncthreads();
    #pragma unroll
    for (int r = 0; r < 4; ++r) {
        const int n = n0 + threadIdx.y + r * 8;
        const int k = k0 + threadIdx.x;
        Wt[(size_t)n * Kpad + k] = __float2half(t[threadIdx.x][threadIdx.y + r * 8]);
    }
}

__global__ __launch_bounds__(256) void zero_kernel(float* __restrict__ p, int n)
{
    const int i = blockIdx.x * 256 + threadIdx.x;
    if (i < n) p[i] = 0.f;
}

// ----------------------------------------------------------------------------
// Ragged segment softmax + weighted pooling. score_i = relu(raw_i + b5).
// ----------------------------------------------------------------------------
__global__ __launch_bounds__(256) void attnpool_kernel(
    const f16* __restrict__ H, const float* __restrict__ raw,
    const float* __restrict__ b5, const int* __restrict__ lengths,
    float* __restrict__ pooled)
{
    const int seg = blockIdx.y;
    const int t = threadIdx.x;
    const int d = blockIdx.x * 256 + t;
    const float b5v = b5[0];

    int start = 0;
    for (int s = 0; s < seg; s++) start += lengths[s];
    const int len = lengths[seg];

    __shared__ float red[256];

    float m = -INFINITY;
    for (int i = t; i < len; i += 256)
        m = fmaxf(m, fmaxf(raw[start + i] + b5v, 0.f));
    red[t] = m; __syncthreads();
    #pragma unroll
    for (int o = 128; o > 0; o >>= 1) {
        if (t < o) red[t] = fmaxf(red[t], red[t + o]);
        __syncthreads();
    }
    m = red[0]; __syncthreads();

    float ds = 0.f;
    for (int i = t; i < len; i += 256)
        ds += __expf(fmaxf(raw[start + i] + b5v, 0.f) - m);
    red[t] = ds; __syncthreads();
    #pragma unroll
    for (int o = 128; o > 0; o >>= 1) {
        if (t < o) red[t] += red[t + o];
        __syncthreads();
    }
    const float denom = red[0];

    const f16* __restrict__ hp = H + (size_t)start * HID + d;
    const float* __restrict__ sp = raw + start;
    float acc = 0.f;
    for (int i = 0; i < len; ++i) {
        const float w = __expf(fmaxf(sp[i] + b5v, 0.f) - m);
        acc = fmaf(w, __half2float(hp[(size_t)i * HID]), acc);
    }
    pooled[seg * HID + d] = acc / denom;
}

// ----------------------------------------------------------------------------
// fp32 SIMT GEMM for the small head (256x1024 @ 1024x1024)
// ----------------------------------------------------------------------------
#define TILE 64
#define KT   16

__global__ __launch_bounds__(256) void gemm_bias_act_kernel(
    const float* __restrict__ A, const float* __restrict__ B,
    const float* __restrict__ bias, float* __restrict__ C,
    int N, int K, int M, int do_relu)
{
    __shared__ float As[KT][TILE + 1];
    __shared__ float Bs[KT][TILE];

    const int tx = threadIdx.x, ty = threadIdx.y;
    const int tid = ty * 16 + tx;
    const int row0 = blockIdx.y * TILE;
    const int col0 = blockIdx.x * TILE;
    const int ar = tid >> 4, ak = tid & 15;
    const int bc = tid & 63, bk = tid >> 6;

    float acc[4][4];
    #pragma unroll
    for (int i = 0; i < 4; i++)
        #pragma unroll
        for (int j = 0; j < 4; j++) acc[i][j] = 0.f;

    for (int k0 = 0; k0 < K; k0 += KT) {
        #pragma unroll
        for (int q = 0; q < 4; q++) {
            const int r = ar + q * 16;
            const int gk = k0 + ak;
            As[ak][r] = (gk < K) ? A[(size_t)(row0 + r) * K + gk] : 0.f;
        }
        #pragma unroll
        for (int q = 0; q < 4; q++) {
            const int kk = bk + q * 4;
            const int gk = k0 + kk;
            Bs[kk][bc] = (gk < K) ? B[(size_t)gk * M + (col0 + bc)] : 0.f;
        }
        __syncthreads();
        #pragma unroll
        for (int kk = 0; kk < KT; kk++) {
            float a[4];
            #pragma unroll
            for (int i = 0; i < 4; i++) a[i] = As[kk][ty * 4 + i];
            const float4 bv = *reinterpret_cast<const float4*>(&Bs[kk][tx * 4]);
            const float b[4] = {bv.x, bv.y, bv.z, bv.w};
            #pragma unroll
            for (int i = 0; i < 4; i++)
                #pragma unroll
                for (int j = 0; j < 4; j++)
                    acc[i][j] = fmaf(a[i], b[j], acc[i][j]);
        }
        __syncthreads();
    }
    #pragma unroll
    for (int i = 0; i < 4; i++) {
        const int r = row0 + ty * 4 + i;
        #pragma unroll
        for (int j = 0; j < 4; j++) {
            const int c = col0 + tx * 4 + j;
            float v = acc[i][j] + bias[c];
            if (do_relu) v = fmaxf(v, 0.f);
            C[(size_t)r * M + c] = v;
        }
    }
}

__global__ void final_kernel(
    const float* __restrict__ T, const float* __restrict__ W7,
    const float* __restrict__ b7, float* __restrict__ out)
{
    const int row = blockIdx.x;
    const int j = threadIdx.y;
    const int lane = threadIdx.x;
    const float* tr = T + (size_t)row * HID;
    float s = 0.f;
    #pragma unroll 8
    for (int k = lane; k < HID; k += 32) s = fmaf(tr[k], W7[k * NCLS + j], s);
    #pragma unroll
    for (int o = 16; o > 0; o >>= 1) s += __shfl_xor_sync(0xffffffffu, s, o);
    if (lane == 0) out[row * NCLS + j] = s + b7[j];
}

// ----------------------------------------------------------------------------
// Launcher
// ----------------------------------------------------------------------------
extern "C" void kernel_launch(void* const* d_in, const int* in_sizes, int n_in,
                              void* d_out, int out_size)
{
    const float* x  = (const float*)d_in[0];
    const float* W1 = (const float*)d_in[1];
    const float* b1 = (const float*)d_in[2];
    const float* W2 = (const float*)d_in[3];
    const float* b2 = (const float*)d_in[4];
    const float* W3 = (const float*)d_in[5];
    const float* b3 = (const float*)d_in[6];
    const float* W4 = (const float*)d_in[7];
    const float* b4 = (const float*)d_in[8];
    const float* W5 = (const float*)d_in[9];
    const float* b5 = (const float*)d_in[10];
    const float* W6 = (const float*)d_in[11];
    const float* b6 = (const float*)d_in[12];
    const float* W7 = (const float*)d_in[13];
    const float* b7 = (const float*)d_in[14];
    const int* lengths = (const int*)d_in[15];
    float* out = (float*)d_out;

    f16 *xp, *A, *B, *W1t, *Wt;
    float *scores_raw, *pooled, *tmp6;
    cudaGetSymbolAddress((void**)&xp, g_xp);
    cudaGetSymbolAddress((void**)&A,  g_A);
    cudaGetSymbolAddress((void**)&B,  g_B);
    cudaGetSymbolAddress((void**)&W1t, g_W1t);
    cudaGetSymbolAddress((void**)&Wt, g_Wt);
    cudaGetSymbolAddress((void**)&scores_raw, g_scores_raw);
    cudaGetSymbolAddress((void**)&pooled, g_pooled);
    cudaGetSymbolAddress((void**)&tmp6, g_tmp6);

    cudaFuncSetAttribute(gemm_mma_kernel,
                         cudaFuncAttributeMaxDynamicSharedMemorySize, GEMM_SMEM);

    // prep
    convert_x_kernel<<<(TOTAL_N * K1P) / 256, 256>>>(x, xp);
    transpose_w_kernel<<<dim3(HID / 32, K1P / 32), dim3(32, 8)>>>(
        W1, FEAT, K1P, W1t);
    transpose_w_kernel<<<dim3(HID / 32, HID / 32), dim3(32, 8)>>>(
        W2, HID, HID, Wt + 0 * HID * HID);
    transpose_w_kernel<<<dim3(HID / 32, HID / 32), dim3(32, 8)>>>(
        W3, HID, HID, Wt + 1 * HID * HID);
    transpose_w_kernel<<<dim3(HID / 32, HID / 32), dim3(32, 8)>>>(
        W4, HID, HID, Wt + 2 * HID * HID);
    zero_kernel<<<TOTAL_N / 256, 256>>>(scores_raw, TOTAL_N);

    const dim3 gemm_grid(HID / BN, TOTAL_N / BM);   // (4, 1024)

    gemm_mma_kernel<<<gemm_grid, 512, GEMM_SMEM>>>(
        xp, W1t, b1, A, nullptr, nullptr, K1P);
    gemm_mma_kernel<<<gemm_grid, 512, GEMM_SMEM>>>(
        A, Wt + 0 * HID * HID, b2, B, nullptr, nullptr, HID);
    gemm_mma_kernel<<<gemm_grid, 512, GEMM_SMEM>>>(
        B, Wt + 1 * HID * HID, b3, A, nullptr, nullptr, HID);
    gemm_mma_kernel<<<gemm_grid, 512, GEMM_SMEM>>>(
        A, Wt + 2 * HID * HID, b4, B, W5, scores_raw, HID);

    attnpool_kernel<<<dim3(HID / 256, NSEG), 256>>>(
        B, scores_raw, b5, lengths, pooled);

    gemm_bias_act_kernel<<<dim3(HID / TILE, NSEG / TILE), dim3(16, 16)>>>(
        pooled, W6, b6, tmp6, NSEG, HID, HID, 1);
    final_kernel<<<NSEG, dim3(32, NCLS)>>>(tmp6, W7, b7, out);

    (void)in_sizes; (void)n_in; (void)out_size;
}

// round 6
// speedup vs baseline: 7.9190x; 1.1321x over previous
#include <cuda_runtime.h>
#include <cuda_fp16.h>
#include <math.h>
#include <stdint.h>

// ----------------------------------------------------------------------------
// Dnn_with_Attention on sm_103 (family-generic: mma.sync HMMA path).
// Pure fp16 operands, fp32 accumulate. 128x128 CTA tile, 256 threads,
// 2 CTAs/SM, 4-stage cp.async pipeline, ldmatrix.x4 fragment loads.
// W5 attention-logit GEMV fused into layer-4 epilogue.
// ----------------------------------------------------------------------------

#define TOTAL_N 131072
#define HID     1024
#define FEAT    78
#define K1P     128
#define NSEG    256
#define NCLS    10

#define BM 128
#define BN 128
#define BKC 32                        // K elems per chunk
#define STAGES 4
#define ROWB 80                       // 32 fp16 = 64B + 16B pad
#define A_BYTES (BM * ROWB)           // 10240
#define B_BYTES (BN * ROWB)           // 10240
#define STAGE_BYTES (A_BYTES + B_BYTES)        // 20480
#define GEMM_SMEM (STAGES * STAGE_BYTES)       // 81920

typedef __half f16;

// ------------------------------- scratch -----------------------------------
__device__ f16 g_xp[(size_t)TOTAL_N * K1P];
__device__ f16 g_A[(size_t)TOTAL_N * HID];
__device__ f16 g_B[(size_t)TOTAL_N * HID];
__device__ f16 g_W1t[HID * K1P];
__device__ f16 g_Wt[3][HID * HID];
__device__ float g_scores_raw[TOTAL_N];
__device__ float g_pooled[NSEG * HID];
__device__ float g_tmp6[NSEG * HID];

// ------------------------------ helpers ------------------------------------
__device__ __forceinline__ uint32_t smem_u32(const void* p) {
    uint32_t a;
    asm("{ .reg .u64 t; cvta.to.shared.u64 t, %1; cvt.u32.u64 %0, t; }"
        : "=r"(a) : "l"(p));
    return a;
}
__device__ __forceinline__ void cp16(uint32_t dst, const void* src) {
    asm volatile("cp.async.cg.shared.global [%0], [%1], 16;"
                 :: "r"(dst), "l"(src) : "memory");
}
__device__ __forceinline__ void cp_commit() {
    asm volatile("cp.async.commit_group;" ::: "memory");
}
template <int N>
__device__ __forceinline__ void cp_wait() {
    asm volatile("cp.async.wait_group %0;" :: "n"(N) : "memory");
}
__device__ __forceinline__ void ldmx4(uint32_t* r, uint32_t addr) {
    asm volatile("ldmatrix.sync.aligned.m8n8.x4.shared.b16 {%0,%1,%2,%3}, [%4];"
                 : "=r"(r[0]), "=r"(r[1]), "=r"(r[2]), "=r"(r[3]) : "r"(addr));
}
__device__ __forceinline__ void mma_f16(float* c, const uint32_t* a,
                                        const uint32_t* b) {
    asm volatile(
        "mma.sync.aligned.m16n8k16.row.col.f32.f16.f16.f32 "
        "{%0,%1,%2,%3}, {%4,%5,%6,%7}, {%8,%9}, {%0,%1,%2,%3};"
        : "+f"(c[0]), "+f"(c[1]), "+f"(c[2]), "+f"(c[3])
        : "r"(a[0]), "r"(a[1]), "r"(a[2]), "r"(a[3]), "r"(b[0]), "r"(b[1]));
}

// ----------------------------------------------------------------------------
// HMMA GEMM: C[M,1024] = relu(A[M,K] @ Bt[1024,K]^T + bias), fp16 in, fp32 acc.
// Optional fused W5 dots -> atomicAdd(scores_raw) (layer 4).
// grid = (1024/BN, M/BM), block = 256 (8 warps, each 32x64), 2 CTAs/SM.
// ----------------------------------------------------------------------------
__global__ void __launch_bounds__(256, 2) gemm_mma_kernel(
    const f16* __restrict__ A, const f16* __restrict__ Bt,
    const float* __restrict__ bias, f16* __restrict__ C,
    const float* __restrict__ W5, float* __restrict__ scores_raw,
    int K)
{
    extern __shared__ char smem[];
    const uint32_t sbase = smem_u32(smem);
    const int tid = threadIdx.x;
    const int lane = tid & 31;
    const int wid = tid >> 5;
    const int wm = (wid & 3) * 32;     // 4 warps over m (4 x 32 = 128)
    const int wn = (wid >> 2) * 64;    // 2 warps over n (2 x 64 = 128)
    const int m0 = blockIdx.y * BM;
    const int n0 = blockIdx.x * BN;
    const int NC = K / BKC;

    // ldmatrix lane-address components
    const int a_row = lane & 15;
    const int a_kb  = (lane >> 4) * 16;
    const int b_row = (lane & 7) + 8 * (lane >> 4);
    const int b_kb  = ((lane >> 3) & 1) * 16;

    float acc[2][8][4];
    #pragma unroll
    for (int i = 0; i < 2; i++)
        #pragma unroll
        for (int j = 0; j < 8; j++)
            #pragma unroll
            for (int q = 0; q < 4; q++) acc[i][j][q] = 0.f;

    auto load_chunk = [&](int stage, int kc) {
        const uint32_t sd = sbase + stage * STAGE_BYTES;
        const int k0 = kc * BKC;
        // A tile: 512 x 16B transfers (2 per thread)
        #pragma unroll
        for (int j = 0; j < 2; ++j) {
            const int idx = tid + 256 * j;
            const int row = idx >> 2;
            const int c16 = idx & 3;
            cp16(sd + row * ROWB + c16 * 16,
                 A + (size_t)(m0 + row) * K + k0 + c16 * 8);
        }
        // B tile: 512 x 16B transfers (2 per thread)
        #pragma unroll
        for (int j = 0; j < 2; ++j) {
            const int idx = tid + 256 * j;
            const int row = idx >> 2;
            const int c16 = idx & 3;
            cp16(sd + A_BYTES + row * ROWB + c16 * 16,
                 Bt + (size_t)(n0 + row) * K + k0 + c16 * 8);
        }
    };

    #pragma unroll
    for (int c = 0; c < STAGES - 1; ++c) {
        if (c < NC) load_chunk(c, c);
        cp_commit();
    }

    for (int c = 0; c < NC; ++c) {
        cp_wait<STAGES - 2>();
        __syncthreads();

        const int lc = c + STAGES - 1;
        if (lc < NC) load_chunk(lc % STAGES, lc);
        cp_commit();

        const uint32_t st = sbase + (c % STAGES) * STAGE_BYTES;
        #pragma unroll
        for (int k16 = 0; k16 < 2; ++k16) {
            const int xb = k16 * 32;
            uint32_t a[2][4], b[8][2];
            #pragma unroll
            for (int mf = 0; mf < 2; ++mf)
                ldmx4(a[mf], st + (wm + mf * 16 + a_row) * ROWB + xb + a_kb);
            #pragma unroll
            for (int p = 0; p < 4; ++p) {
                uint32_t r[4];
                ldmx4(r, st + A_BYTES +
                          (wn + p * 16 + b_row) * ROWB + xb + b_kb);
                b[p * 2][0] = r[0]; b[p * 2][1] = r[1];
                b[p * 2 + 1][0] = r[2]; b[p * 2 + 1][1] = r[3];
            }
            #pragma unroll
            for (int mf = 0; mf < 2; ++mf)
                #pragma unroll
                for (int nf = 0; nf < 8; ++nf)
                    mma_f16(acc[mf][nf], a[mf], b[nf]);
        }
    }

    // epilogue: bias + relu + fp16 store (+ fused W5 dot)
    const int gr = lane >> 2;
    float sdot[2][2];
    sdot[0][0] = sdot[0][1] = sdot[1][0] = sdot[1][1] = 0.f;

    #pragma unroll
    for (int mf = 0; mf < 2; ++mf) {
        const int r0 = m0 + wm + mf * 16 + gr;
        #pragma unroll
        for (int nf = 0; nf < 8; ++nf) {
            const int c0 = n0 + wn + nf * 8 + (lane & 3) * 2;
            const float bv0 = bias[c0], bv1 = bias[c0 + 1];
            const float v00 = fmaxf(acc[mf][nf][0] + bv0, 0.f);
            const float v01 = fmaxf(acc[mf][nf][1] + bv1, 0.f);
            const float v10 = fmaxf(acc[mf][nf][2] + bv0, 0.f);
            const float v11 = fmaxf(acc[mf][nf][3] + bv1, 0.f);

            if (W5 != nullptr) {
                const float w0 = W5[c0], w1 = W5[c0 + 1];
                sdot[mf][0] = fmaf(v00, w0, fmaf(v01, w1, sdot[mf][0]));
                sdot[mf][1] = fmaf(v10, w0, fmaf(v11, w1, sdot[mf][1]));
            }

            const uint32_t p0 =
                ((uint32_t)__half_as_ushort(__float2half(v01)) << 16) |
                __half_as_ushort(__float2half(v00));
            const uint32_t p1 =
                ((uint32_t)__half_as_ushort(__float2half(v11)) << 16) |
                __half_as_ushort(__float2half(v10));
            *reinterpret_cast<uint32_t*>(C + (size_t)r0 * HID + c0) = p0;
            *reinterpret_cast<uint32_t*>(C + (size_t)(r0 + 8) * HID + c0) = p1;
        }
    }

    if (W5 != nullptr) {
        #pragma unroll
        for (int mf = 0; mf < 2; ++mf) {
            float s0 = sdot[mf][0], s1 = sdot[mf][1];
            s0 += __shfl_xor_sync(0xffffffffu, s0, 1);
            s0 += __shfl_xor_sync(0xffffffffu, s0, 2);
            s1 += __shfl_xor_sync(0xffffffffu, s1, 1);
            s1 += __shfl_xor_sync(0xffffffffu, s1, 2);
            if ((lane & 3) == 0) {
                const int r0 = m0 + wm + mf * 16 + gr;
                atomicAdd(&scores_raw[r0], s0);
                atomicAdd(&scores_raw[r0 + 8], s1);
            }
        }
    }
}

// ----------------------------------------------------------------------------
// Prep kernels
// ----------------------------------------------------------------------------
__global__ __launch_bounds__(256) void convert_x_kernel(
    const float* __restrict__ x, f16* __restrict__ xp)
{
    const size_t idx = (size_t)blockIdx.x * 256 + threadIdx.x;
    const int row = (int)(idx >> 7);
    const int k = (int)(idx & 127);
    xp[idx] = __float2half((k < FEAT) ? x[(size_t)row * FEAT + k] : 0.f);
}

__global__ __launch_bounds__(256) void transpose_w_kernel(
    const float* __restrict__ W, int Kin, int Kpad, f16* __restrict__ Wt)
{
    __shared__ float t[32][33];
    const int n0 = blockIdx.x * 32;
    const int k0 = blockIdx.y * 32;
    #pragma unroll
    for (int r = 0; r < 4; ++r) {
        const int k = k0 + threadIdx.y + r * 8;
        t[threadIdx.y + r * 8][threadIdx.x] =
            (k < Kin) ? W[(size_t)k * HID + n0 + threadIdx.x] : 0.f;
    }
    __syncthreads();
    #pragma unroll
    for (int r = 0; r < 4; ++r) {
        const int n = n0 + threadIdx.y + r * 8;
        const int k = k0 + threadIdx.x;
        Wt[(size_t)n * Kpad + k] = __float2half(t[threadIdx.x][threadIdx.y + r * 8]);
    }
}

__global__ __launch_bounds__(256) void zero_kernel(float* __restrict__ p, int n)
{
    const int i = blockIdx.x * 256 + threadIdx.x;
    if (i < n) p[i] = 0.f;
}

// ----------------------------------------------------------------------------
// Ragged segment softmax + weighted pooling. score_i = relu(raw_i + b5).
// ----------------------------------------------------------------------------
__global__ __launch_bounds__(256) void attnpool_kernel(
    const f16* __restrict__ H, const float* __restrict__ raw,
    const float* __restrict__ b5, const int* __restrict__ lengths,
    float* __restrict__ pooled)
{
    const int seg = blockIdx.y;
    const int t = threadIdx.x;
    const int d = blockIdx.x * 256 + t;
    const float b5v = b5[0];

    int start = 0;
    for (int s = 0; s < seg; s++) start += lengths[s];
    const int len = lengths[seg];

    __shared__ float red[256];

    float m = -INFINITY;
    for (int i = t; i < len; i += 256)
        m = fmaxf(m, fmaxf(raw[start + i] + b5v, 0.f));
    red[t] = m; __syncthreads();
    #pragma unroll
    for (int o = 128; o > 0; o >>= 1) {
        if (t < o) red[t] = fmaxf(red[t], red[t + o]);
        __syncthreads();
    }
    m = red[0]; __syncthreads();

    float ds = 0.f;
    for (int i = t; i < len; i += 256)
        ds += __expf(fmaxf(raw[start + i] + b5v, 0.f) - m);
    red[t] = ds; __syncthreads();
    #pragma unroll
    for (int o = 128; o > 0; o >>= 1) {
        if (t < o) red[t] += red[t + o];
        __syncthreads();
    }
    const float denom = red[0];

    const f16* __restrict__ hp = H + (size_t)start * HID + d;
    const float* __restrict__ sp = raw + start;
    float acc = 0.f;
    for (int i = 0; i < len; ++i) {
        const float w = __expf(fmaxf(sp[i] + b5v, 0.f) - m);
        acc = fmaf(w, __half2float(hp[(size_t)i * HID]), acc);
    }
    pooled[seg * HID + d] = acc / denom;
}

// ----------------------------------------------------------------------------
// fp32 SIMT GEMM for the small head (256x1024 @ 1024x1024)
// ----------------------------------------------------------------------------
#define TILE 64
#define KT   16

__global__ __launch_bounds__(256) void gemm_bias_act_kernel(
    const float* __restrict__ A, const float* __restrict__ B,
    const float* __restrict__ bias, float* __restrict__ C,
    int N, int K, int M, int do_relu)
{
    __shared__ float As[KT][TILE + 1];
    __shared__ float Bs[KT][TILE];

    const int tx = threadIdx.x, ty = threadIdx.y;
    const int tid = ty * 16 + tx;
    const int row0 = blockIdx.y * TILE;
    const int col0 = blockIdx.x * TILE;
    const int ar = tid >> 4, ak = tid & 15;
    const int bc = tid & 63, bk = tid >> 6;

    float acc[4][4];
    #pragma unroll
    for (int i = 0; i < 4; i++)
        #pragma unroll
        for (int j = 0; j < 4; j++) acc[i][j] = 0.f;

    for (int k0 = 0; k0 < K; k0 += KT) {
        #pragma unroll
        for (int q = 0; q < 4; q++) {
            const int r = ar + q * 16;
            const int gk = k0 + ak;
            As[ak][r] = (gk < K) ? A[(size_t)(row0 + r) * K + gk] : 0.f;
        }
        #pragma unroll
        for (int q = 0; q < 4; q++) {
            const int kk = bk + q * 4;
            const int gk = k0 + kk;
            Bs[kk][bc] = (gk < K) ? B[(size_t)gk * M + (col0 + bc)] : 0.f;
        }
        __syncthreads();
        #pragma unroll
        for (int kk = 0; kk < KT; kk++) {
            float a[4];
            #pragma unroll
            for (int i = 0; i < 4; i++) a[i] = As[kk][ty * 4 + i];
            const float4 bv = *reinterpret_cast<const float4*>(&Bs[kk][tx * 4]);
            const float b[4] = {bv.x, bv.y, bv.z, bv.w};
            #pragma unroll
            for (int i = 0; i < 4; i++)
                #pragma unroll
                for (int j = 0; j < 4; j++)
                    acc[i][j] = fmaf(a[i], b[j], acc[i][j]);
        }
        __syncthreads();
    }
    #pragma unroll
    for (int i = 0; i < 4; i++) {
        const int r = row0 + ty * 4 + i;
        #pragma unroll
        for (int j = 0; j < 4; j++) {
            const int c = col0 + tx * 4 + j;
            float v = acc[i][j] + bias[c];
            if (do_relu) v = fmaxf(v, 0.f);
            C[(size_t)r * M + c] = v;
        }
    }
}

__global__ void final_kernel(
    const float* __restrict__ T, const float* __restrict__ W7,
    const float* __restrict__ b7, float* __restrict__ out)
{
    const int row = blockIdx.x;
    const int j = threadIdx.y;
    const int lane = threadIdx.x;
    const float* tr = T + (size_t)row * HID;
    float s = 0.f;
    #pragma unroll 8
    for (int k = lane; k < HID; k += 32) s = fmaf(tr[k], W7[k * NCLS + j], s);
    #pragma unroll
    for (int o = 16; o > 0; o >>= 1) s += __shfl_xor_sync(0xffffffffu, s, o);
    if (lane == 0) out[row * NCLS + j] = s + b7[j];
}

// ----------------------------------------------------------------------------
// Launcher
// ----------------------------------------------------------------------------
extern "C" void kernel_launch(void* const* d_in, const int* in_sizes, int n_in,
                              void* d_out, int out_size)
{
    const float* x  = (const float*)d_in[0];
    const float* W1 = (const float*)d_in[1];
    const float* b1 = (const float*)d_in[2];
    const float* W2 = (const float*)d_in[3];
    const float* b2 = (const float*)d_in[4];
    const float* W3 = (const float*)d_in[5];
    const float* b3 = (const float*)d_in[6];
    const float* W4 = (const float*)d_in[7];
    const float* b4 = (const float*)d_in[8];
    const float* W5 = (const float*)d_in[9];
    const float* b5 = (const float*)d_in[10];
    const float* W6 = (const float*)d_in[11];
    const float* b6 = (const float*)d_in[12];
    const float* W7 = (const float*)d_in[13];
    const float* b7 = (const float*)d_in[14];
    const int* lengths = (const int*)d_in[15];
    float* out = (float*)d_out;

    f16 *xp, *A, *B, *W1t, *Wt;
    float *scores_raw, *pooled, *tmp6;
    cudaGetSymbolAddress((void**)&xp, g_xp);
    cudaGetSymbolAddress((void**)&A,  g_A);
    cudaGetSymbolAddress((void**)&B,  g_B);
    cudaGetSymbolAddress((void**)&W1t, g_W1t);
    cudaGetSymbolAddress((void**)&Wt, g_Wt);
    cudaGetSymbolAddress((void**)&scores_raw, g_scores_raw);
    cudaGetSymbolAddress((void**)&pooled, g_pooled);
    cudaGetSymbolAddress((void**)&tmp6, g_tmp6);

    cudaFuncSetAttribute(gemm_mma_kernel,
                         cudaFuncAttributeMaxDynamicSharedMemorySize, GEMM_SMEM);

    // prep
    convert_x_kernel<<<(TOTAL_N * K1P) / 256, 256>>>(x, xp);
    transpose_w_kernel<<<dim3(HID / 32, K1P / 32), dim3(32, 8)>>>(
        W1, FEAT, K1P, W1t);
    transpose_w_kernel<<<dim3(HID / 32, HID / 32), dim3(32, 8)>>>(
        W2, HID, HID, Wt + 0 * HID * HID);
    transpose_w_kernel<<<dim3(HID / 32, HID / 32), dim3(32, 8)>>>(
        W3, HID, HID, Wt + 1 * HID * HID);
    transpose_w_kernel<<<dim3(HID / 32, HID / 32), dim3(32, 8)>>>(
        W4, HID, HID, Wt + 2 * HID * HID);
    zero_kernel<<<TOTAL_N / 256, 256>>>(scores_raw, TOTAL_N);

    const dim3 gemm_grid(HID / BN, TOTAL_N / BM);   // (8, 1024)

    gemm_mma_kernel<<<gemm_grid, 256, GEMM_SMEM>>>(
        xp, W1t, b1, A, nullptr, nullptr, K1P);
    gemm_mma_kernel<<<gemm_grid, 256, GEMM_SMEM>>>(
        A, Wt + 0 * HID * HID, b2, B, nullptr, nullptr, HID);
    gemm_mma_kernel<<<gemm_grid, 256, GEMM_SMEM>>>(
        B, Wt + 1 * HID * HID, b3, A, nullptr, nullptr, HID);
    gemm_mma_kernel<<<gemm_grid, 256, GEMM_SMEM>>>(
        A, Wt + 2 * HID * HID, b4, B, W5, scores_raw, HID);

    attnpool_kernel<<<dim3(HID / 256, NSEG), 256>>>(
        B, scores_raw, b5, lengths, pooled);

    gemm_bias_act_kernel<<<dim3(HID / TILE, NSEG / TILE), dim3(16, 16)>>>(
        pooled, W6, b6, tmp6, NSEG, HID, HID, 1);
    final_kernel<<<NSEG, dim3(32, NCLS)>>>(tmp6, W7, b7, out);

    (void)in_sizes; (void)n_in; (void)out_size;
}

// round 7
// speedup vs baseline: 8.4609x; 1.0684x over previous
#include <cuda_runtime.h>
#include <cuda_fp16.h>
#include <math.h>
#include <stdint.h>

// ----------------------------------------------------------------------------
// Dnn_with_Attention on sm_103 (family-generic: mma.sync HMMA path).
// Pure fp16 operands, fp32 accumulate. 128x128 CTA tile, 256 threads,
// 2 CTAs/SM, BKC=64 chunks (half the syncs), 3-stage cp.async pipeline.
// W5 attention-logit GEMV fused into layer-4 epilogue.
// ----------------------------------------------------------------------------

#define TOTAL_N 131072
#define HID     1024
#define FEAT    78
#define K1P     128
#define NSEG    256
#define NCLS    10

#define BM 128
#define BN 128
#define BKC 64                        // K elems per chunk (128 bytes/row)
#define STAGES 3
#define ROWB 144                      // 128B data + 16B pad (conflict-free)
#define A_BYTES (BM * ROWB)           // 18432
#define B_BYTES (BN * ROWB)           // 18432
#define STAGE_BYTES (A_BYTES + B_BYTES)        // 36864
#define GEMM_SMEM (STAGES * STAGE_BYTES)       // 110592

typedef __half f16;

// ------------------------------- scratch -----------------------------------
__device__ f16 g_xp[(size_t)TOTAL_N * K1P];
__device__ f16 g_A[(size_t)TOTAL_N * HID];
__device__ f16 g_B[(size_t)TOTAL_N * HID];
__device__ f16 g_W1t[HID * K1P];
__device__ f16 g_Wt[3][HID * HID];
__device__ float g_scores_raw[TOTAL_N];
__device__ float g_pooled[NSEG * HID];
__device__ float g_tmp6[NSEG * HID];

// ------------------------------ helpers ------------------------------------
__device__ __forceinline__ uint32_t smem_u32(const void* p) {
    uint32_t a;
    asm("{ .reg .u64 t; cvta.to.shared.u64 t, %1; cvt.u32.u64 %0, t; }"
        : "=r"(a) : "l"(p));
    return a;
}
__device__ __forceinline__ void cp16(uint32_t dst, const void* src) {
    asm volatile("cp.async.cg.shared.global [%0], [%1], 16;"
                 :: "r"(dst), "l"(src) : "memory");
}
__device__ __forceinline__ void cp_commit() {
    asm volatile("cp.async.commit_group;" ::: "memory");
}
template <int N>
__device__ __forceinline__ void cp_wait() {
    asm volatile("cp.async.wait_group %0;" :: "n"(N) : "memory");
}
__device__ __forceinline__ void ldmx4(uint32_t* r, uint32_t addr) {
    asm volatile("ldmatrix.sync.aligned.m8n8.x4.shared.b16 {%0,%1,%2,%3}, [%4];"
                 : "=r"(r[0]), "=r"(r[1]), "=r"(r[2]), "=r"(r[3]) : "r"(addr));
}
__device__ __forceinline__ void mma_f16(float* c, const uint32_t* a,
                                        const uint32_t* b) {
    asm volatile(
        "mma.sync.aligned.m16n8k16.row.col.f32.f16.f16.f32 "
        "{%0,%1,%2,%3}, {%4,%5,%6,%7}, {%8,%9}, {%0,%1,%2,%3};"
        : "+f"(c[0]), "+f"(c[1]), "+f"(c[2]), "+f"(c[3])
        : "r"(a[0]), "r"(a[1]), "r"(a[2]), "r"(a[3]), "r"(b[0]), "r"(b[1]));
}

// ----------------------------------------------------------------------------
// HMMA GEMM: C[M,1024] = relu(A[M,K] @ Bt[1024,K]^T + bias), fp16 in, fp32 acc.
// Optional fused W5 dots -> atomicAdd(scores_raw) (layer 4).
// grid = (1024/BN, M/BM), block = 256 (8 warps, each 32x64), 2 CTAs/SM.
// ----------------------------------------------------------------------------
__global__ void __launch_bounds__(256, 2) gemm_mma_kernel(
    const f16* __restrict__ A, const f16* __restrict__ Bt,
    const float* __restrict__ bias, f16* __restrict__ C,
    const float* __restrict__ W5, float* __restrict__ scores_raw,
    int K)
{
    extern __shared__ char smem[];
    const uint32_t sbase = smem_u32(smem);
    const int tid = threadIdx.x;
    const int lane = tid & 31;
    const int wid = tid >> 5;
    const int wm = (wid & 3) * 32;     // 4 warps over m
    const int wn = (wid >> 2) * 64;    // 2 warps over n
    const int m0 = blockIdx.y * BM;
    const int n0 = blockIdx.x * BN;
    const int NC = K / BKC;

    // ldmatrix lane-address components
    const int a_row = lane & 15;
    const int a_kb  = (lane >> 4) * 16;
    const int b_row = (lane & 7) + 8 * (lane >> 4);
    const int b_kb  = ((lane >> 3) & 1) * 16;

    float acc[2][8][4];
    #pragma unroll
    for (int i = 0; i < 2; i++)
        #pragma unroll
        for (int j = 0; j < 8; j++)
            #pragma unroll
            for (int q = 0; q < 4; q++) acc[i][j][q] = 0.f;

    // per-chunk: A 1024 transfers + B 1024 transfers = 8 per thread
    auto load_chunk = [&](int stage, int kc) {
        const uint32_t sd = sbase + stage * STAGE_BYTES;
        const int k0 = kc * BKC;
        const int row = tid >> 3;          // 0..31 (+32 per j in A), reuse
        #pragma unroll
        for (int j = 0; j < 4; ++j) {
            const int idx = tid + 256 * j;     // 0..1023
            const int r = idx >> 3;
            const int c16 = idx & 7;
            cp16(sd + r * ROWB + c16 * 16,
                 A + (size_t)(m0 + r) * K + k0 + c16 * 8);
        }
        #pragma unroll
        for (int j = 0; j < 4; ++j) {
            const int idx = tid + 256 * j;
            const int r = idx >> 3;
            const int c16 = idx & 7;
            cp16(sd + A_BYTES + r * ROWB + c16 * 16,
                 Bt + (size_t)(n0 + r) * K + k0 + c16 * 8);
        }
        (void)row;
    };

    #pragma unroll
    for (int c = 0; c < STAGES - 1; ++c) {
        if (c < NC) load_chunk(c, c);
        cp_commit();
    }

    for (int c = 0; c < NC; ++c) {
        cp_wait<STAGES - 2>();
        __syncthreads();

        const int lc = c + STAGES - 1;
        if (lc < NC) load_chunk(lc % STAGES, lc);
        cp_commit();

        const uint32_t st = sbase + (c % STAGES) * STAGE_BYTES;
        #pragma unroll
        for (int k16 = 0; k16 < 4; ++k16) {
            const int xb = k16 * 32;
            uint32_t a[2][4], b[8][2];
            #pragma unroll
            for (int mf = 0; mf < 2; ++mf)
                ldmx4(a[mf], st + (wm + mf * 16 + a_row) * ROWB + xb + a_kb);
            #pragma unroll
            for (int p = 0; p < 4; ++p) {
                uint32_t r[4];
                ldmx4(r, st + A_BYTES +
                          (wn + p * 16 + b_row) * ROWB + xb + b_kb);
                b[p * 2][0] = r[0]; b[p * 2][1] = r[1];
                b[p * 2 + 1][0] = r[2]; b[p * 2 + 1][1] = r[3];
            }
            #pragma unroll
            for (int mf = 0; mf < 2; ++mf)
                #pragma unroll
                for (int nf = 0; nf < 8; ++nf)
                    mma_f16(acc[mf][nf], a[mf], b[nf]);
        }
    }

    // epilogue: bias + relu + fp16 store (+ fused W5 dot)
    const int gr = lane >> 2;
    float sdot[2][2];
    sdot[0][0] = sdot[0][1] = sdot[1][0] = sdot[1][1] = 0.f;

    #pragma unroll
    for (int mf = 0; mf < 2; ++mf) {
        const int r0 = m0 + wm + mf * 16 + gr;
        #pragma unroll
        for (int nf = 0; nf < 8; ++nf) {
            const int c0 = n0 + wn + nf * 8 + (lane & 3) * 2;
            const float bv0 = bias[c0], bv1 = bias[c0 + 1];
            const float v00 = fmaxf(acc[mf][nf][0] + bv0, 0.f);
            const float v01 = fmaxf(acc[mf][nf][1] + bv1, 0.f);
            const float v10 = fmaxf(acc[mf][nf][2] + bv0, 0.f);
            const float v11 = fmaxf(acc[mf][nf][3] + bv1, 0.f);

            if (W5 != nullptr) {
                const float w0 = W5[c0], w1 = W5[c0 + 1];
                sdot[mf][0] = fmaf(v00, w0, fmaf(v01, w1, sdot[mf][0]));
                sdot[mf][1] = fmaf(v10, w0, fmaf(v11, w1, sdot[mf][1]));
            }

            const uint32_t p0 =
                ((uint32_t)__half_as_ushort(__float2half(v01)) << 16) |
                __half_as_ushort(__float2half(v00));
            const uint32_t p1 =
                ((uint32_t)__half_as_ushort(__float2half(v11)) << 16) |
                __half_as_ushort(__float2half(v10));
            *reinterpret_cast<uint32_t*>(C + (size_t)r0 * HID + c0) = p0;
            *reinterpret_cast<uint32_t*>(C + (size_t)(r0 + 8) * HID + c0) = p1;
        }
    }

    if (W5 != nullptr) {
        #pragma unroll
        for (int mf = 0; mf < 2; ++mf) {
            float s0 = sdot[mf][0], s1 = sdot[mf][1];
            s0 += __shfl_xor_sync(0xffffffffu, s0, 1);
            s0 += __shfl_xor_sync(0xffffffffu, s0, 2);
            s1 += __shfl_xor_sync(0xffffffffu, s1, 1);
            s1 += __shfl_xor_sync(0xffffffffu, s1, 2);
            if ((lane & 3) == 0) {
                const int r0 = m0 + wm + mf * 16 + gr;
                atomicAdd(&scores_raw[r0], s0);
                atomicAdd(&scores_raw[r0 + 8], s1);
            }
        }
    }
}

// ----------------------------------------------------------------------------
// Prep kernels
// ----------------------------------------------------------------------------
__global__ __launch_bounds__(256) void convert_x_kernel(
    const float* __restrict__ x, f16* __restrict__ xp)
{
    const size_t idx = (size_t)blockIdx.x * 256 + threadIdx.x;
    const int row = (int)(idx >> 7);
    const int k = (int)(idx & 127);
    xp[idx] = __float2half((k < FEAT) ? x[(size_t)row * FEAT + k] : 0.f);
}

__global__ __launch_bounds__(256) void transpose_w_kernel(
    const float* __restrict__ W, int Kin, int Kpad, f16* __restrict__ Wt)
{
    __shared__ float t[32][33];
    const int n0 = blockIdx.x * 32;
    const int k0 = blockIdx.y * 32;
    #pragma unroll
    for (int r = 0; r < 4; ++r) {
        const int k = k0 + threadIdx.y + r * 8;
        t[threadIdx.y + r * 8][threadIdx.x] =
            (k < Kin) ? W[(size_t)k * HID + n0 + threadIdx.x] : 0.f;
    }
    __syncthreads();
    #pragma unroll
    for (int r = 0; r < 4; ++r) {
        const int n = n0 + threadIdx.y + r * 8;
        const int k = k0 + threadIdx.x;
        Wt[(size_t)n * Kpad + k] = __float2half(t[threadIdx.x][threadIdx.y + r * 8]);
    }
}

__global__ __launch_bounds__(256) void zero_kernel(float* __restrict__ p, int n)
{
    const int i = blockIdx.x * 256 + threadIdx.x;
    if (i < n) p[i] = 0.f;
}

// ----------------------------------------------------------------------------
// Ragged segment softmax + weighted pooling. score_i = relu(raw_i + b5).
// ----------------------------------------------------------------------------
__global__ __launch_bounds__(256) void attnpool_kernel(
    const f16* __restrict__ H, const float* __restrict__ raw,
    const float* __restrict__ b5, const int* __restrict__ lengths,
    float* __restrict__ pooled)
{
    const int seg = blockIdx.y;
    const int t = threadIdx.x;
    const int d = blockIdx.x * 256 + t;
    const float b5v = b5[0];

    int start = 0;
    for (int s = 0; s < seg; s++) start += lengths[s];
    const int len = lengths[seg];

    __shared__ float red[256];

    float m = -INFINITY;
    for (int i = t; i < len; i += 256)
        m = fmaxf(m, fmaxf(raw[start + i] + b5v, 0.f));
    red[t] = m; __syncthreads();
    #pragma unroll
    for (int o = 128; o > 0; o >>= 1) {
        if (t < o) red[t] = fmaxf(red[t], red[t + o]);
        __syncthreads();
    }
    m = red[0]; __syncthreads();

    float ds = 0.f;
    for (int i = t; i < len; i += 256)
        ds += __expf(fmaxf(raw[start + i] + b5v, 0.f) - m);
    red[t] = ds; __syncthreads();
    #pragma unroll
    for (int o = 128; o > 0; o >>= 1) {
        if (t < o) red[t] += red[t + o];
        __syncthreads();
    }
    const float denom = red[0];

    const f16* __restrict__ hp = H + (size_t)start * HID + d;
    const float* __restrict__ sp = raw + start;
    float acc = 0.f;
    for (int i = 0; i < len; ++i) {
        const float w = __expf(fmaxf(sp[i] + b5v, 0.f) - m);
        acc = fmaf(w, __half2float(hp[(size_t)i * HID]), acc);
    }
    pooled[seg * HID + d] = acc / denom;
}

// ----------------------------------------------------------------------------
// fp32 SIMT GEMM for the small head (256x1024 @ 1024x1024)
// ----------------------------------------------------------------------------
#define TILE 64
#define KT   16

__global__ __launch_bounds__(256) void gemm_bias_act_kernel(
    const float* __restrict__ A, const float* __restrict__ B,
    const float* __restrict__ bias, float* __restrict__ C,
    int N, int K, int M, int do_relu)
{
    __shared__ float As[KT][TILE + 1];
    __shared__ float Bs[KT][TILE];

    const int tx = threadIdx.x, ty = threadIdx.y;
    const int tid = ty * 16 + tx;
    const int row0 = blockIdx.y * TILE;
    const int col0 = blockIdx.x * TILE;
    const int ar = tid >> 4, ak = tid & 15;
    const int bc = tid & 63, bk = tid >> 6;

    float acc[4][4];
    #pragma unroll
    for (int i = 0; i < 4; i++)
        #pragma unroll
        for (int j = 0; j < 4; j++) acc[i][j] = 0.f;

    for (int k0 = 0; k0 < K; k0 += KT) {
        #pragma unroll
        for (int q = 0; q < 4; q++) {
            const int r = ar + q * 16;
            const int gk = k0 + ak;
            As[ak][r] = (gk < K) ? A[(size_t)(row0 + r) * K + gk] : 0.f;
        }
        #pragma unroll
        for (int q = 0; q < 4; q++) {
            const int kk = bk + q * 4;
            const int gk = k0 + kk;
            Bs[kk][bc] = (gk < K) ? B[(size_t)gk * M + (col0 + bc)] : 0.f;
        }
        __syncthreads();
        #pragma unroll
        for (int kk = 0; kk < KT; kk++) {
            float a[4];
            #pragma unroll
            for (int i = 0; i < 4; i++) a[i] = As[kk][ty * 4 + i];
            const float4 bv = *reinterpret_cast<const float4*>(&Bs[kk][tx * 4]);
            const float b[4] = {bv.x, bv.y, bv.z, bv.w};
            #pragma unroll
            for (int i = 0; i < 4; i++)
                #pragma unroll
                for (int j = 0; j < 4; j++)
                    acc[i][j] = fmaf(a[i], b[j], acc[i][j]);
        }
        __syncthreads();
    }
    #pragma unroll
    for (int i = 0; i < 4; i++) {
        const int r = row0 + ty * 4 + i;
        #pragma unroll
        for (int j = 0; j < 4; j++) {
            const int c = col0 + tx * 4 + j;
            float v = acc[i][j] + bias[c];
            if (do_relu) v = fmaxf(v, 0.f);
            C[(size_t)r * M + c] = v;
        }
    }
}

__global__ void final_kernel(
    const float* __restrict__ T, const float* __restrict__ W7,
    const float* __restrict__ b7, float* __restrict__ out)
{
    const int row = blockIdx.x;
    const int j = threadIdx.y;
    const int lane = threadIdx.x;
    const float* tr = T + (size_t)row * HID;
    float s = 0.f;
    #pragma unroll 8
    for (int k = lane; k < HID; k += 32) s = fmaf(tr[k], W7[k * NCLS + j], s);
    #pragma unroll
    for (int o = 16; o > 0; o >>= 1) s += __shfl_xor_sync(0xffffffffu, s, o);
    if (lane == 0) out[row * NCLS + j] = s + b7[j];
}

// ----------------------------------------------------------------------------
// Launcher
// ----------------------------------------------------------------------------
extern "C" void kernel_launch(void* const* d_in, const int* in_sizes, int n_in,
                              void* d_out, int out_size)
{
    const float* x  = (const float*)d_in[0];
    const float* W1 = (const float*)d_in[1];
    const float* b1 = (const float*)d_in[2];
    const float* W2 = (const float*)d_in[3];
    const float* b2 = (const float*)d_in[4];
    const float* W3 = (const float*)d_in[5];
    const float* b3 = (const float*)d_in[6];
    const float* W4 = (const float*)d_in[7];
    const float* b4 = (const float*)d_in[8];
    const float* W5 = (const float*)d_in[9];
    const float* b5 = (const float*)d_in[10];
    const float* W6 = (const float*)d_in[11];
    const float* b6 = (const float*)d_in[12];
    const float* W7 = (const float*)d_in[13];
    const float* b7 = (const float*)d_in[14];
    const int* lengths = (const int*)d_in[15];
    float* out = (float*)d_out;

    f16 *xp, *A, *B, *W1t, *Wt;
    float *scores_raw, *pooled, *tmp6;
    cudaGetSymbolAddress((void**)&xp, g_xp);
    cudaGetSymbolAddress((void**)&A,  g_A);
    cudaGetSymbolAddress((void**)&B,  g_B);
    cudaGetSymbolAddress((void**)&W1t, g_W1t);
    cudaGetSymbolAddress((void**)&Wt, g_Wt);
    cudaGetSymbolAddress((void**)&scores_raw, g_scores_raw);
    cudaGetSymbolAddress((void**)&pooled, g_pooled);
    cudaGetSymbolAddress((void**)&tmp6, g_tmp6);

    cudaFuncSetAttribute(gemm_mma_kernel,
                         cudaFuncAttributeMaxDynamicSharedMemorySize, GEMM_SMEM);

    // prep
    convert_x_kernel<<<(TOTAL_N * K1P) / 256, 256>>>(x, xp);
    transpose_w_kernel<<<dim3(HID / 32, K1P / 32), dim3(32, 8)>>>(
        W1, FEAT, K1P, W1t);
    transpose_w_kernel<<<dim3(HID / 32, HID / 32), dim3(32, 8)>>>(
        W2, HID, HID, Wt + 0 * HID * HID);
    transpose_w_kernel<<<dim3(HID / 32, HID / 32), dim3(32, 8)>>>(
        W3, HID, HID, Wt + 1 * HID * HID);
    transpose_w_kernel<<<dim3(HID / 32, HID / 32), dim3(32, 8)>>>(
        W4, HID, HID, Wt + 2 * HID * HID);
    zero_kernel<<<TOTAL_N / 256, 256>>>(scores_raw, TOTAL_N);

    const dim3 gemm_grid(HID / BN, TOTAL_N / BM);   // (8, 1024)

    gemm_mma_kernel<<<gemm_grid, 256, GEMM_SMEM>>>(
        xp, W1t, b1, A, nullptr, nullptr, K1P);
    gemm_mma_kernel<<<gemm_grid, 256, GEMM_SMEM>>>(
        A, Wt + 0 * HID * HID, b2, B, nullptr, nullptr, HID);
    gemm_mma_kernel<<<gemm_grid, 256, GEMM_SMEM>>>(
        B, Wt + 1 * HID * HID, b3, A, nullptr, nullptr, HID);
    gemm_mma_kernel<<<gemm_grid, 256, GEMM_SMEM>>>(
        A, Wt + 2 * HID * HID, b4, B, W5, scores_raw, HID);

    attnpool_kernel<<<dim3(HID / 256, NSEG), 256>>>(
        B, scores_raw, b5, lengths, pooled);

    gemm_bias_act_kernel<<<dim3(HID / TILE, NSEG / TILE), dim3(16, 16)>>>(
        pooled, W6, b6, tmp6, NSEG, HID, HID, 1);
    final_kernel<<<NSEG, dim3(32, NCLS)>>>(tmp6, W7, b7, out);

    (void)in_sizes; (void)n_in; (void)out_size;
}